// round 9
// baseline (speedup 1.0000x reference)
#include <cuda_runtime.h>
#include <cstdint>

// Problem constants (fixed by the reference)
#define B_    2
#define T_    512
#define D_    768
#define E_    256
#define P_    65536
#define H1_   768
#define H2_   384
#define NL_   5
#define ROWS_ (B_*E_)          // 512 fused (b,e) rows

#define PL1_SLAB (ROWS_*H1_)   // 393216
#define PL2_SLAB (ROWS_*H2_)   // 196608
#define PU_SLAB  (ROWS_*2*H2_) // 393216

// ---------------- scratch (static device globals; no allocation) ------------
__device__ float g_pooled[ROWS_*D_];        // mean-pooled spans       [512,768]
__device__ float g_eph[NL_*H1_];            // emb @ Wh1[768:]         [5,768]
__device__ float g_ept[NL_*H1_];            // emb @ Wt1[768:]         [5,768]
__device__ float g_Pl1[8*PL1_SLAB];         // L1 partials [net*4+kp]
__device__ float g_Pl2[16*PL2_SLAB];        // L2 partials [net*8+kp]
__device__ float g_head[ROWS_*H2_];         // head_all                [512,384]
__device__ float g_tail[ROWS_*H2_];         // tail_all                [512,384]
__device__ float g_Pu[4*PU_SLAB];           // u partials [kp]
__device__ float g_Vp[32*E_*E_];            // V partials [bo*8+kp][256*256]
__device__ float g_V[4*E_*E_];              // dense biaffine table [bo][h][t]
__device__ float g_lh[ROWS_*2];             // head @ W_lin[:384]
__device__ float g_lt[ROWS_*2];             // tail @ W_lin[384:]

// ---------------- tf32 helpers ----------------------------------------------
__device__ __forceinline__ uint32_t f2tf32(float x) {
    uint32_t r;
    asm("cvt.rna.tf32.f32 %0, %1;" : "=r"(r) : "f"(x));
    return r;
}
__device__ __forceinline__ void mma_tf32(float c[4],
                                         const uint32_t a[4],
                                         const uint32_t b[2]) {
    asm volatile(
        "mma.sync.aligned.m16n8k8.row.col.f32.tf32.tf32.f32 "
        "{%0,%1,%2,%3}, {%4,%5,%6,%7}, {%8,%9}, {%0,%1,%2,%3};"
        : "+f"(c[0]), "+f"(c[1]), "+f"(c[2]), "+f"(c[3])
        : "r"(a[0]), "r"(a[1]), "r"(a[2]), "r"(a[3]), "r"(b[0]), "r"(b[1]));
}
__device__ __forceinline__ void hsplit(float x, uint32_t& h, uint32_t& l) {
    h = f2tf32(x);
    l = f2tf32(x - __uint_as_float(h));
}

// smem: float4 slots.  A: 2 bufs x 128 rows x 8 slots; B: 2 bufs x 64 rows x 8.
// Slot s = c*4+r holds (hi[8c+r], hi[8c+r+4], lo[8c+r], lo[8c+r+4]).
// Swizzle: physical slot = s ^ (row & 7)  -> conflict-free LDS.128/STS.128.
#define A_BUF4 1024            // 128*8 float4
#define B_BUF4 512             // 64*8 float4
#define SM_BYTES ((2*A_BUF4 + 2*B_BUF4)*16)   // 49152

// ---------------- 3xTF32 GEMM core ------------------------------------------
// Block tile 128(M) x 64(N), BK=16, 256 threads = 8 warps (4 m x 2 n),
// warp tile 32x32.  acc += hi*hi + hi*lo + lo*hi  (fp32 accum, ~fp32 accuracy).
// Staging roles: tids 0-127 stage A (1 row, 16 k each); tids 128-255 stage B.
// AMODE: 0 plain A0; 1 relu(A0+A1+A2+A3 + abias[k] + albias[label[row]][k]);
//        2 A0+A1+A2+A3.
// BMODE: 0 NN  B[k][n] at W + (n/segw)*segstride + k*ldb + (n%segw)
//        1 NT  B[n][k] at W + n*ldb + k
// M%128==0, N%64==0, segw%64==0, kslice%16==0.
template<int AMODE, int BMODE>
__device__ __forceinline__ void gemm_core(
    const float* __restrict__ A0, const float* __restrict__ A1,
    const float* __restrict__ A2, const float* __restrict__ A3,
    const float* __restrict__ abias, const int* __restrict__ labels,
    const float* __restrict__ albias, int lda,
    const float* __restrict__ W, int ldb, int segw, int segstride,
    float* __restrict__ C, int N, int kstart, int kslice)
{
    extern __shared__ float4 sm4[];
    float4* As = sm4;             // [buf][row*8 + ss]
    float4* Bs = sm4 + 2*A_BUF4;  // [buf][row*8 + ss]

    const int tid = threadIdx.x;
    const int bm = blockIdx.y*128, bn = blockIdx.x*64;
    const int lane = tid&31, wid = tid>>5;
    const int wm = wid&3, wn = wid>>2;
    const int q = lane>>2, r = lane&3;

    // ---- stager setup ----
    const float* gA0=nullptr; const float* gA1=nullptr;
    const float* gA2=nullptr; const float* gA3=nullptr;
    const float* gbias=nullptr; const float* glb=nullptr;
    const float* gB0=nullptr; const float* gB1=nullptr;
    int b_n0=0, b_s=0, bnt_n=0, bnt_ch=0;
    if (tid < 128) {
        size_t ro = (size_t)(bm+tid)*lda + kstart;
        gA0 = A0 + ro;
        if (AMODE >= 1) { gA1 = A1+ro; gA2 = A2+ro; gA3 = A3+ro; }
        if (AMODE == 1) {
            gbias = abias + kstart;
            glb   = albias + (size_t)labels[bm+tid]*lda + kstart;
        }
    } else {
        int t = tid - 128;
        if (BMODE == 0) {
            int p = t&7, nq = t>>3;          // p: k-pair, nq: n-group of 4
            int c = p>>2, rr = p&3;
            int kb = c*8 + rr;
            b_s = c*4 + rr;
            b_n0 = nq*4;
            int seg = bn/segw;
            const float* base = W + (size_t)seg*segstride + (bn - seg*segw) + b_n0;
            gB0 = base + (size_t)(kstart+kb)*ldb;
            gB1 = base + (size_t)(kstart+kb+4)*ldb;
        } else {
            bnt_n = t>>1; bnt_ch = t&1;
            gB0 = W + (size_t)(bn+bnt_n)*ldb + kstart + bnt_ch*8;
        }
    }

    float va[16];

    auto fetch = [&](int t) {
        if (tid < 128) {
            const float4* p = (const float4*)(gA0 + t*16);
            float4 x0=p[0], x1=p[1], x2=p[2], x3=p[3];
            va[0]=x0.x; va[1]=x0.y; va[2]=x0.z; va[3]=x0.w;
            va[4]=x1.x; va[5]=x1.y; va[6]=x1.z; va[7]=x1.w;
            va[8]=x2.x; va[9]=x2.y; va[10]=x2.z; va[11]=x2.w;
            va[12]=x3.x; va[13]=x3.y; va[14]=x3.z; va[15]=x3.w;
            if (AMODE >= 1) {
                const float4* p1 = (const float4*)(gA1 + t*16);
                const float4* p2 = (const float4*)(gA2 + t*16);
                const float4* p3 = (const float4*)(gA3 + t*16);
                #pragma unroll
                for (int j = 0; j < 4; j++) {
                    float4 y = p1[j], z = p2[j], w = p3[j];
                    va[j*4+0] = (va[j*4+0] + y.x) + (z.x + w.x);
                    va[j*4+1] = (va[j*4+1] + y.y) + (z.y + w.y);
                    va[j*4+2] = (va[j*4+2] + y.z) + (z.z + w.z);
                    va[j*4+3] = (va[j*4+3] + y.w) + (z.w + w.w);
                }
            }
            if (AMODE == 1) {
                const float4* pb = (const float4*)(gbias + t*16);
                const float4* pl = (const float4*)(glb + t*16);
                #pragma unroll
                for (int j = 0; j < 4; j++) {
                    float4 bsv = pb[j], lv = pl[j];
                    va[j*4+0] = fmaxf(va[j*4+0] + bsv.x + lv.x, 0.f);
                    va[j*4+1] = fmaxf(va[j*4+1] + bsv.y + lv.y, 0.f);
                    va[j*4+2] = fmaxf(va[j*4+2] + bsv.z + lv.z, 0.f);
                    va[j*4+3] = fmaxf(va[j*4+3] + bsv.w + lv.w, 0.f);
                }
            }
        } else if (BMODE == 0) {
            float4 y0 = *(const float4*)(gB0 + (size_t)t*16*ldb);
            float4 y1 = *(const float4*)(gB1 + (size_t)t*16*ldb);
            va[0]=y0.x; va[1]=y0.y; va[2]=y0.z; va[3]=y0.w;
            va[4]=y1.x; va[5]=y1.y; va[6]=y1.z; va[7]=y1.w;
        } else {
            const float4* p = (const float4*)(gB0 + t*16);
            float4 y0=p[0], y1=p[1];
            va[0]=y0.x; va[1]=y0.y; va[2]=y0.z; va[3]=y0.w;
            va[4]=y1.x; va[5]=y1.y; va[6]=y1.z; va[7]=y1.w;
        }
    };

    auto stage = [&](int buf) {
        if (tid < 128) {
            float4* dst = As + buf*A_BUF4 + tid*8;
            int h7 = tid&7;
            #pragma unroll
            for (int c = 0; c < 2; c++)
                #pragma unroll
                for (int rr = 0; rr < 4; rr++) {
                    uint32_t h0,l0,h1,l1;
                    hsplit(va[c*8+rr], h0, l0);
                    hsplit(va[c*8+rr+4], h1, l1);
                    dst[(c*4+rr)^h7] = make_float4(
                        __uint_as_float(h0), __uint_as_float(h1),
                        __uint_as_float(l0), __uint_as_float(l1));
                }
        } else if (BMODE == 0) {
            float4* dst = Bs + buf*B_BUF4;
            #pragma unroll
            for (int i = 0; i < 4; i++) {
                int n = b_n0 + i;
                uint32_t h0,l0,h1,l1;
                hsplit(va[i], h0, l0);
                hsplit(va[4+i], h1, l1);
                dst[n*8 + (b_s^(n&7))] = make_float4(
                    __uint_as_float(h0), __uint_as_float(h1),
                    __uint_as_float(l0), __uint_as_float(l1));
            }
        } else {
            float4* dst = Bs + buf*B_BUF4 + bnt_n*8;
            int h7 = bnt_n&7;
            #pragma unroll
            for (int rr = 0; rr < 4; rr++) {
                uint32_t h0,l0,h1,l1;
                hsplit(va[rr], h0, l0);
                hsplit(va[rr+4], h1, l1);
                dst[(bnt_ch*4+rr)^h7] = make_float4(
                    __uint_as_float(h0), __uint_as_float(h1),
                    __uint_as_float(l0), __uint_as_float(l1));
            }
        }
    };

    float acc[2][4][4] = {};

    auto compute = [&](int buf) {
        #pragma unroll
        for (int c = 0; c < 2; c++) {
            uint32_t ah[2][4], al[2][4];
            #pragma unroll
            for (int f = 0; f < 2; f++) {
                int m0 = wm*32 + f*16 + q;            // m0&7 == q
                int ss = (c*4+r) ^ q;
                float4 fa = As[buf*A_BUF4 + m0*8 + ss];
                float4 fb = As[buf*A_BUF4 + (m0+8)*8 + ss];
                ah[f][0]=__float_as_uint(fa.x); ah[f][2]=__float_as_uint(fa.y);
                al[f][0]=__float_as_uint(fa.z); al[f][2]=__float_as_uint(fa.w);
                ah[f][1]=__float_as_uint(fb.x); ah[f][3]=__float_as_uint(fb.y);
                al[f][1]=__float_as_uint(fb.z); al[f][3]=__float_as_uint(fb.w);
            }
            #pragma unroll
            for (int g = 0; g < 4; g++) {
                int n = wn*32 + g*8 + q;              // n&7 == q
                float4 fbv = Bs[buf*B_BUF4 + n*8 + ((c*4+r)^q)];
                uint32_t bh[2] = {__float_as_uint(fbv.x), __float_as_uint(fbv.y)};
                uint32_t bl[2] = {__float_as_uint(fbv.z), __float_as_uint(fbv.w)};
                #pragma unroll
                for (int f = 0; f < 2; f++) {
                    mma_tf32(acc[f][g], ah[f], bh);
                    mma_tf32(acc[f][g], ah[f], bl);
                    mma_tf32(acc[f][g], al[f], bh);
                }
            }
        }
    };

    fetch(0); stage(0);
    __syncthreads();
    const int nk = kslice >> 4;
    for (int t = 0; t < nk; t++) {
        int cur = t & 1, nxt = cur ^ 1;
        if (t + 1 < nk) fetch(t+1);
        compute(cur);
        if (t + 1 < nk) stage(nxt);
        __syncthreads();
    }

    // epilogue (m16n8 frag layout: c0 (q,2r) c1 (q,2r+1) c2 (q+8,2r) c3 (q+8,2r+1))
    #pragma unroll
    for (int f = 0; f < 2; f++) {
        int row0 = bm + wm*32 + f*16 + q;
        #pragma unroll
        for (int g = 0; g < 4; g++) {
            int ncol = bn + wn*32 + g*8 + r*2;
            *(float2*)(C + (size_t)row0*N + ncol) =
                make_float2(acc[f][g][0], acc[f][g][1]);
            *(float2*)(C + (size_t)(row0+8)*N + ncol) =
                make_float2(acc[f][g][2], acc[f][g][3]);
        }
    }
}

// ---------------- GEMM wrappers ---------------------------------------------
// L1: Pl1[net*4+kp] = pooled @ W1[net] slice   grid(12,4,8)
__global__ __launch_bounds__(256, 2) void k_l1(
    const float* __restrict__ pooled,
    const float* __restrict__ Wh1, const float* __restrict__ Wt1,
    float* __restrict__ Pl1)
{
    int z = blockIdx.z, net = z >> 2, kp = z & 3;
    gemm_core<0,0>(pooled, nullptr, nullptr, nullptr,
                   nullptr, nullptr, nullptr, D_,
                   net ? Wt1 : Wh1, H1_, H1_, 0,
                   Pl1 + (size_t)z*PL1_SLAB, H1_, kp*192, 192);
}

// L2: Pl2[net*8+kp] = relu(sum4 Pl1 + b1 + lb) @ W2[net]   grid(6,4,16)
__global__ __launch_bounds__(256, 2) void k_l2(
    const float* __restrict__ Pl1,
    const float* __restrict__ Wh2, const float* __restrict__ Wt2,
    const float* __restrict__ bh1, const float* __restrict__ bt1,
    const int* __restrict__ labels,
    const float* __restrict__ eph, const float* __restrict__ ept,
    float* __restrict__ Pl2)
{
    int z = blockIdx.z, net = z >> 3, kp = z & 7;
    const float* base = Pl1 + (size_t)(net*4)*PL1_SLAB;
    gemm_core<1,0>(base, base + PL1_SLAB, base + 2*PL1_SLAB, base + 3*PL1_SLAB,
                   net ? bt1 : bh1, labels, net ? ept : eph, H1_,
                   net ? Wt2 : Wh2, H2_, H2_, 0,
                   Pl2 + (size_t)z*PL2_SLAB, H2_, kp*96, 96);
}

// u: Pu[kp] = head @ W_bil (segmented)   grid(12,4,4)
__global__ __launch_bounds__(256, 2) void k_u(
    const float* __restrict__ head, const float* __restrict__ Wbil,
    float* __restrict__ Pu)
{
    int kp = blockIdx.z;
    gemm_core<0,0>(head, nullptr, nullptr, nullptr,
                   nullptr, nullptr, nullptr, H2_,
                   Wbil, H2_, H2_, H2_*H2_,
                   Pu + (size_t)kp*PU_SLAB, 2*H2_, kp*96, 96);
}

// V: Vp[bo*8+kp] = (sum4 Pu)[b,:,o-slice] @ tail_b^T   grid(4,2,32)
__global__ __launch_bounds__(256, 2) void k_V(
    const float* __restrict__ Pu, const float* __restrict__ tail,
    float* __restrict__ Vp)
{
    int z = blockIdx.z, bo = z >> 3, kp = z & 7;
    int b = bo >> 1, o = bo & 1;
    const float* base = Pu + (size_t)(b*E_)*(2*H2_) + o*H2_;
    gemm_core<2,1>(base, base + PU_SLAB, base + 2*PU_SLAB, base + 3*PU_SLAB,
                   nullptr, nullptr, nullptr, 2*H2_,
                   tail + (size_t)b*E_*H2_, H2_, 0, 0,
                   Vp + (size_t)z*E_*E_, E_, kp*48, 48);
}

// ---------------- 1) span mean-pooling --------------------------------------
__global__ void pool_kernel(const float* __restrict__ hs,
                            const int* __restrict__ st,
                            const int* __restrict__ en) {
    int be = blockIdx.x;             // 0..511
    int b  = be >> 8;
    int s  = st[be];
    int len = en[be] - s;
    int cl  = len < 1 ? 1 : len;
    float inv = 1.0f / (float)cl;
    const float* base = hs + ((size_t)(b*T_ + s))*D_;
    for (int d = threadIdx.x; d < D_; d += blockDim.x) {
        float acc = 0.f;
        for (int t = 0; t < len; t++) acc += base[(size_t)t*D_ + d];
        g_pooled[(size_t)be*D_ + d] = acc * inv;
    }
}

// ---------------- 2) per-label projection through W1[768:] for BOTH nets ----
__global__ void labelproj2_kernel(const float* __restrict__ emb,
                                  const float* __restrict__ Wh1,
                                  const float* __restrict__ Wt1) {
    int gid = blockIdx.x*blockDim.x + threadIdx.x;  // 2*5*768 = 7680
    if (gid >= 2*NL_*H1_) return;
    int half = gid / (NL_*H1_);
    int r    = gid - half*(NL_*H1_);
    int l = r / H1_, n = r - l*H1_;
    const float* W1 = half ? Wt1 : Wh1;
    const float* wp = W1 + (size_t)D_*H1_ + n;      // rows 768..1535, col n
    const float* ep = emb + (size_t)l*D_;
    float acc = 0.f;
    #pragma unroll 4
    for (int k = 0; k < D_; k++) acc += ep[k] * wp[(size_t)k*H1_];
    if (half) g_ept[r] = acc; else g_eph[r] = acc;
}

// ---------------- combine L2: head/tail = relu(sum8 Pl2 + bias) -------------
__global__ void combine_l2(const float* __restrict__ Pl2,
                           const float* __restrict__ bh2,
                           const float* __restrict__ bt2,
                           float* __restrict__ head, float* __restrict__ tail)
{
    int idx = blockIdx.x*blockDim.x + threadIdx.x;
    int pq = ROWS_*H2_/4;
    if (idx >= 2*pq) return;
    int net = idx >= pq ? 1 : 0;
    int r = idx - net*pq;
    int col = (r*4) % H2_;
    const float* bs = net ? bt2 : bh2;
    float4 v = make_float4(bs[col], bs[col+1], bs[col+2], bs[col+3]);
    #pragma unroll
    for (int kp = 0; kp < 8; kp++) {
        float4 a = ((const float4*)(Pl2 + (size_t)(net*8+kp)*PL2_SLAB))[r];
        v.x += a.x; v.y += a.y; v.z += a.z; v.w += a.w;
    }
    v.x = fmaxf(v.x, 0.f); v.y = fmaxf(v.y, 0.f);
    v.z = fmaxf(v.z, 0.f); v.w = fmaxf(v.w, 0.f);
    (net ? (float4*)tail : (float4*)head)[r] = v;
}

// ---------------- combine V partials -> dense table -------------------------
__global__ void combine_V(const float* __restrict__ Vp, float* __restrict__ V) {
    int idx = blockIdx.x*blockDim.x + threadIdx.x;   // 4*65536/4 = 65536
    const int per = E_*E_/4;
    if (idx >= 4*per) return;
    int bo = idx / per, rr = idx - bo*per;
    float4 v = make_float4(0.f, 0.f, 0.f, 0.f);
    #pragma unroll
    for (int kp = 0; kp < 8; kp++) {
        float4 a = ((const float4*)(Vp + (size_t)(bo*8+kp)*E_*E_))[rr];
        v.x += a.x; v.y += a.y; v.z += a.z; v.w += a.w;
    }
    ((float4*)V)[idx] = v;
}

// ---------------- per-entity linear terms lh/lt -----------------------------
__global__ void lhlt_kernel(const float* __restrict__ Wlin) {
    int gid  = blockIdx.x*blockDim.x + threadIdx.x;
    int w    = gid >> 5;            // entity row 0..511
    int lane = gid & 31;
    if (w >= ROWS_) return;
    float s0=0.f, s1=0.f, s2=0.f, s3=0.f;
    for (int j = lane; j < H2_; j += 32) {
        float hv = g_head[(size_t)w*H2_ + j];
        float tv = g_tail[(size_t)w*H2_ + j];
        s0 += hv * Wlin[j*2+0];
        s1 += hv * Wlin[j*2+1];
        s2 += tv * Wlin[(H2_+j)*2+0];
        s3 += tv * Wlin[(H2_+j)*2+1];
    }
    #pragma unroll
    for (int off = 16; off > 0; off >>= 1) {
        s0 += __shfl_down_sync(0xffffffffu, s0, off);
        s1 += __shfl_down_sync(0xffffffffu, s1, off);
        s2 += __shfl_down_sync(0xffffffffu, s2, off);
        s3 += __shfl_down_sync(0xffffffffu, s3, off);
    }
    if (lane == 0) {
        g_lh[w*2+0] = s0; g_lh[w*2+1] = s1;
        g_lt[w*2+0] = s2; g_lt[w*2+1] = s3;
    }
}

// ---------------- final per-pair lookup -------------------------------------
__global__ void gather_kernel(const int* __restrict__ hidx,
                              const int* __restrict__ tidx,
                              const float* __restrict__ blin,
                              float* __restrict__ out) {
    int gid = blockIdx.x*blockDim.x + threadIdx.x;   // B*P = 131072
    if (gid >= B_*P_) return;
    int b = gid >> 16;
    int h = hidx[gid];
    int t = tidx[gid];
    int rh = (b << 8) + h;
    int rt = (b << 8) + t;
    size_t off = (size_t)(h << 8) + t;
    float v0 = g_V[((size_t)(b*2+0) << 16) + off];
    float v1 = g_V[((size_t)(b*2+1) << 16) + off];
    float2 r;
    r.x = v0 + g_lh[rh*2+0] + g_lt[rt*2+0] + blin[0];
    r.y = v1 + g_lh[rh*2+1] + g_lt[rt*2+1] + blin[1];
    ((float2*)out)[gid] = r;
}

// ---------------- launch ----------------------------------------------------
extern "C" void kernel_launch(void* const* d_in, const int* in_sizes, int n_in,
                              void* d_out, int out_size) {
    const float* hs   = (const float*)d_in[0];
    const float* emb  = (const float*)d_in[1];
    const float* Wh1  = (const float*)d_in[2];
    const float* bh1  = (const float*)d_in[3];
    const float* Wh2  = (const float*)d_in[4];
    const float* bh2  = (const float*)d_in[5];
    const float* Wt1  = (const float*)d_in[6];
    const float* bt1  = (const float*)d_in[7];
    const float* Wt2  = (const float*)d_in[8];
    const float* bt2  = (const float*)d_in[9];
    const float* Wbil = (const float*)d_in[10];
    const float* Wlin = (const float*)d_in[11];
    const float* blin = (const float*)d_in[12];
    const int*   est  = (const int*)d_in[13];
    const int*   een  = (const int*)d_in[14];
    const int*   elab = (const int*)d_in[15];
    const int*   hidx = (const int*)d_in[16];
    const int*   tidx = (const int*)d_in[17];

    float *p_pooled, *p_eph, *p_ept, *p_Pl1, *p_Pl2, *p_head, *p_tail,
          *p_Pu, *p_Vp, *p_V;
    cudaGetSymbolAddress((void**)&p_pooled, g_pooled);
    cudaGetSymbolAddress((void**)&p_eph,    g_eph);
    cudaGetSymbolAddress((void**)&p_ept,    g_ept);
    cudaGetSymbolAddress((void**)&p_Pl1,    g_Pl1);
    cudaGetSymbolAddress((void**)&p_Pl2,    g_Pl2);
    cudaGetSymbolAddress((void**)&p_head,   g_head);
    cudaGetSymbolAddress((void**)&p_tail,   g_tail);
    cudaGetSymbolAddress((void**)&p_Pu,     g_Pu);
    cudaGetSymbolAddress((void**)&p_Vp,     g_Vp);
    cudaGetSymbolAddress((void**)&p_V,      g_V);

    // allow 48KB+ dynamic smem (non-stream API; capture-safe)
    cudaFuncSetAttribute(k_l1, cudaFuncAttributeMaxDynamicSharedMemorySize, SM_BYTES);
    cudaFuncSetAttribute(k_l2, cudaFuncAttributeMaxDynamicSharedMemorySize, SM_BYTES);
    cudaFuncSetAttribute(k_u,  cudaFuncAttributeMaxDynamicSharedMemorySize, SM_BYTES);
    cudaFuncSetAttribute(k_V,  cudaFuncAttributeMaxDynamicSharedMemorySize, SM_BYTES);

    // 1) span mean pooling -> g_pooled [512,768]
    pool_kernel<<<ROWS_, 256>>>(hs, est, een);

    // 2) label projections for BOTH nets in one launch
    labelproj2_kernel<<<(2*NL_*H1_ + 255)/256, 256>>>(emb, Wh1, Wt1);

    // 3) L1 partials (2 nets x split-K4): 384 blocks
    k_l1<<<dim3(H1_/64, ROWS_/128, 8), 256, SM_BYTES>>>(p_pooled, Wh1, Wt1, p_Pl1);

    // 4) L2 partials with fused L1-combine (2 nets x split-K8): 384 blocks
    k_l2<<<dim3(H2_/64, ROWS_/128, 16), 256, SM_BYTES>>>(
        p_Pl1, Wh2, Wt2, bh1, bt1, elab, p_eph, p_ept, p_Pl2);

    // 5) combine L2 partials -> head/tail
    combine_l2<<<(2*ROWS_*H2_/4 + 255)/256, 256>>>(p_Pl2, bh2, bt2, p_head, p_tail);

    // 6) per-entity linear terms
    lhlt_kernel<<<(ROWS_*32 + 255)/256, 256>>>(Wlin);

    // 7) u partials = head @ W_bil (segmented-B), split-K4: 192 blocks
    k_u<<<dim3((2*H2_)/64, ROWS_/128, 4), 256, SM_BYTES>>>(p_head, Wbil, p_Pu);

    // 8) V partials = (sum4 Pu) @ tail^T, per (b,o) x split-K8: 256 blocks
    k_V<<<dim3(E_/64, E_/128, 32), 256, SM_BYTES>>>(p_Pu, p_tail, p_Vp);

    // 9) combine V partials -> dense table
    combine_V<<<(4*E_*E_/4 + 255)/256, 256>>>(p_Vp, p_V);

    // 10) per-pair lookup + linear terms + bias
    gather_kernel<<<(B_*P_ + 255)/256, 256>>>(hidx, tidx, blin, (float*)d_out);
}

// round 10
// speedup vs baseline: 1.2222x; 1.2222x over previous
#include <cuda_runtime.h>
#include <cstdint>

// Problem constants (fixed by the reference)
#define B_    2
#define T_    512
#define D_    768
#define E_    256
#define P_    65536
#define H1_   768
#define H2_   384
#define NL_   5
#define ROWS_ (B_*E_)          // 512 fused (b,e) rows

#define PL1_SLAB (ROWS_*H1_)   // 393216
#define PL2_SLAB (ROWS_*H2_)   // 196608
#define PU_SLAB  (ROWS_*2*H2_) // 393216

// ---------------- scratch (static device globals; no allocation) ------------
__device__ float g_pooled[ROWS_*D_];        // mean-pooled spans       [512,768]
__device__ float g_eph[NL_*H1_];            // emb @ Wh1[768:]         [5,768]
__device__ float g_ept[NL_*H1_];            // emb @ Wt1[768:]         [5,768]
__device__ float g_Pl1[8*PL1_SLAB];         // L1 partials [net*4+kp]
__device__ float g_Pl2[16*PL2_SLAB];        // L2 partials [net*8+kp]
__device__ float g_head[ROWS_*H2_];         // head_all                [512,384]
__device__ float g_tail[ROWS_*H2_];         // tail_all                [512,384]
__device__ float g_Pu[4*PU_SLAB];           // u partials [kp]
__device__ float g_Vp[32*E_*E_];            // V partials [bo*8+kp][256*256]
__device__ float g_V[4*E_*E_];              // dense biaffine table [bo][h][t]
__device__ float g_lh[ROWS_*2];             // head @ W_lin[:384]
__device__ float g_lt[ROWS_*2];             // tail @ W_lin[384:]

// ---------------- tf32 helpers ----------------------------------------------
__device__ __forceinline__ uint32_t f2tf32(float x) {
    uint32_t r;
    asm("cvt.rna.tf32.f32 %0, %1;" : "=r"(r) : "f"(x));
    return r;
}
__device__ __forceinline__ void mma_tf32(float c[4],
                                         const uint32_t a[4],
                                         const uint32_t b[2]) {
    asm volatile(
        "mma.sync.aligned.m16n8k8.row.col.f32.tf32.tf32.f32 "
        "{%0,%1,%2,%3}, {%4,%5,%6,%7}, {%8,%9}, {%0,%1,%2,%3};"
        : "+f"(c[0]), "+f"(c[1]), "+f"(c[2]), "+f"(c[3])
        : "r"(a[0]), "r"(a[1]), "r"(a[2]), "r"(a[3]), "r"(b[0]), "r"(b[1]));
}
__device__ __forceinline__ uint32_t ldb32(const float* p) {
    return __float_as_uint(*p);
}

// smem layout (floats):  As stride 20 per row, Bs stride 72 per k-row
#define ASTRIDE 20
#define BSTRIDE 72
#define AS_BUF  (128*ASTRIDE)   // 2560
#define BS_BUF  (16*BSTRIDE)    // 1152
#define SM_AH   0
#define SM_AL   (2*AS_BUF)      // 5120
#define SM_BH   (4*AS_BUF)      // 10240
#define SM_BL   (4*AS_BUF + 2*BS_BUF)  // 12544
#define SM_FLOATS (4*AS_BUF + 4*BS_BUF) // 14848
#define SM_BYTES  (SM_FLOATS*4)         // 59392

// ---------------- 3xTF32 GEMM core (R8-proven; AMODE1 extended to 4 slabs) --
// Block tile 128(M) x 64(N), BK=16, 256 threads = 8 warps (4 m-warps x 2
// n-warps), warp tile 32x32 (2 m-frags x 4 n-frags of m16n8k8).
// Each input split x = hi + lo in tf32 during smem staging; accumulate
// hi*hi + hi*lo + lo*hi in fp32.
// AMODE: 0 = plain A0.
//        1 = relu(A0+A1+A2+A3 + abias[k] + albias[labels[row]][k])
//        2 = A0 + A1 + A2 + A3 (sum of 4 split-K partials)
// BMODE: 0 = NN, B[k][n] at W + (n/segw)*segstride + k*ldb + (n%segw)
//        1 = NT, B[n][k] at W + n*ldb + k
// M%128==0, N%64==0, segw%64==0, kslice%16==0.
template<int AMODE, int BMODE>
__device__ __forceinline__ void gemm_core(
    const float* __restrict__ A0, const float* __restrict__ A1,
    const float* __restrict__ A2, const float* __restrict__ A3,
    const float* __restrict__ abias, const int* __restrict__ labels,
    const float* __restrict__ albias, int lda,
    const float* __restrict__ W, int ldb, int segw, int segstride,
    float* __restrict__ C, int N, int kstart, int kslice)
{
    extern __shared__ float sm[];
    float* AsH = sm + SM_AH;
    float* AsL = sm + SM_AL;
    float* BsH = sm + SM_BH;
    float* BsL = sm + SM_BL;

    const int tid = threadIdx.x;
    const int bm = blockIdx.y * 128, bn = blockIdx.x * 64;
    const int lane = tid & 31, wid = tid >> 5;
    const int wm = wid & 3, wn = wid >> 2;     // 4 x 2 warp grid
    const int q = lane >> 2, r = lane & 3;

    // staging maps
    const int arow = tid >> 1, ac8 = (tid & 1) * 8;   // A: 128 rows x 16 k
    const int brow = tid >> 4, bc4 = (tid & 15) * 4;  // B NN: 16 k x 64 n
    const int nrow = tid >> 2, kc4 = (tid & 3) * 4;   // B NT: 64 n x 16 k

    const float* Ap0 = A0 + (size_t)(bm+arow)*lda + kstart + ac8;
    const float* Ap1 = (AMODE>=1) ? A1 + (size_t)(bm+arow)*lda + kstart + ac8 : nullptr;
    const float* Ap2 = (AMODE>=1) ? A2 + (size_t)(bm+arow)*lda + kstart + ac8 : nullptr;
    const float* Ap3 = (AMODE>=1) ? A3 + (size_t)(bm+arow)*lda + kstart + ac8 : nullptr;
    const float* biasp = (AMODE==1) ? abias + kstart + ac8 : nullptr;
    const float* lbp   = (AMODE==1)
        ? albias + (size_t)labels[bm+arow]*lda + kstart + ac8 : nullptr;

    const float* Wp;
    if (BMODE == 0) {
        int seg = bn / segw;
        Wp = W + (size_t)seg*segstride + (bn - seg*segw)
               + (size_t)(kstart+brow)*ldb + bc4;
    } else {
        Wp = W + (size_t)(bn + nrow)*ldb + kstart + kc4;
    }

    float va[8], vb[4];

    auto fetchA = [&](int t) {
        const float* p = Ap0 + t*16;
        float4 x0 = *(const float4*)p, x1 = *(const float4*)(p+4);
        va[0]=x0.x; va[1]=x0.y; va[2]=x0.z; va[3]=x0.w;
        va[4]=x1.x; va[5]=x1.y; va[6]=x1.z; va[7]=x1.w;
        if (AMODE >= 1) {
            {
                const float* p1 = Ap1 + t*16;
                float4 y0 = *(const float4*)p1, y1 = *(const float4*)(p1+4);
                va[0]+=y0.x; va[1]+=y0.y; va[2]+=y0.z; va[3]+=y0.w;
                va[4]+=y1.x; va[5]+=y1.y; va[6]+=y1.z; va[7]+=y1.w;
            }
            {
                const float* p2 = Ap2 + t*16;
                float4 y0 = *(const float4*)p2, y1 = *(const float4*)(p2+4);
                va[0]+=y0.x; va[1]+=y0.y; va[2]+=y0.z; va[3]+=y0.w;
                va[4]+=y1.x; va[5]+=y1.y; va[6]+=y1.z; va[7]+=y1.w;
            }
            {
                const float* p3 = Ap3 + t*16;
                float4 y0 = *(const float4*)p3, y1 = *(const float4*)(p3+4);
                va[0]+=y0.x; va[1]+=y0.y; va[2]+=y0.z; va[3]+=y0.w;
                va[4]+=y1.x; va[5]+=y1.y; va[6]+=y1.z; va[7]+=y1.w;
            }
        }
        if (AMODE == 1) {
            float4 b0 = *(const float4*)(biasp + t*16), b1 = *(const float4*)(biasp + t*16 + 4);
            float4 l0 = *(const float4*)(lbp + t*16),   l1 = *(const float4*)(lbp + t*16 + 4);
            va[0] = fmaxf(va[0] + b0.x + l0.x, 0.f);
            va[1] = fmaxf(va[1] + b0.y + l0.y, 0.f);
            va[2] = fmaxf(va[2] + b0.z + l0.z, 0.f);
            va[3] = fmaxf(va[3] + b0.w + l0.w, 0.f);
            va[4] = fmaxf(va[4] + b1.x + l1.x, 0.f);
            va[5] = fmaxf(va[5] + b1.y + l1.y, 0.f);
            va[6] = fmaxf(va[6] + b1.z + l1.z, 0.f);
            va[7] = fmaxf(va[7] + b1.w + l1.w, 0.f);
        }
    };
    auto fetchB = [&](int t) {
        float4 w4;
        if (BMODE == 0) w4 = *(const float4*)(Wp + (size_t)t*16*ldb);
        else            w4 = *(const float4*)(Wp + t*16);
        vb[0]=w4.x; vb[1]=w4.y; vb[2]=w4.z; vb[3]=w4.w;
    };
    auto stageA = [&](int buf) {
        int base = buf*AS_BUF + arow*ASTRIDE + ac8;
        #pragma unroll
        for (int j = 0; j < 8; j++) {
            uint32_t h = f2tf32(va[j]);
            AsH[base+j] = __uint_as_float(h);
            AsL[base+j] = __uint_as_float(f2tf32(va[j] - __uint_as_float(h)));
        }
    };
    auto stageB = [&](int buf) {
        if (BMODE == 0) {
            int base = buf*BS_BUF + brow*BSTRIDE + bc4;
            #pragma unroll
            for (int j = 0; j < 4; j++) {
                uint32_t h = f2tf32(vb[j]);
                BsH[base+j] = __uint_as_float(h);
                BsL[base+j] = __uint_as_float(f2tf32(vb[j] - __uint_as_float(h)));
            }
        } else {
            int base = buf*BS_BUF + nrow;
            #pragma unroll
            for (int j = 0; j < 4; j++) {
                uint32_t h = f2tf32(vb[j]);
                BsH[base + (kc4+j)*BSTRIDE] = __uint_as_float(h);
                BsL[base + (kc4+j)*BSTRIDE] = __uint_as_float(f2tf32(vb[j] - __uint_as_float(h)));
            }
        }
    };

    float acc[2][4][4];
    #pragma unroll
    for (int f = 0; f < 2; f++)
        #pragma unroll
        for (int g = 0; g < 4; g++)
            #pragma unroll
            for (int i = 0; i < 4; i++) acc[f][g][i] = 0.f;

    fetchA(0); fetchB(0);
    stageA(0); stageB(0);
    __syncthreads();

    const int nk = kslice >> 4;
    for (int t = 0; t < nk; t++) {
        int cur = t & 1, nxt = cur ^ 1;
        if (t + 1 < nk) { fetchA(t+1); fetchB(t+1); }

        #pragma unroll
        for (int k0 = 0; k0 < 16; k0 += 8) {
            uint32_t ah[2][4], al[2][4], bh[4][2], bl[4][2];
            #pragma unroll
            for (int f = 0; f < 2; f++) {
                int m = wm*32 + f*16 + q;
                int ab = cur*AS_BUF + m*ASTRIDE + k0 + r;
                ah[f][0] = ldb32(AsH + ab);
                ah[f][1] = ldb32(AsH + ab + 8*ASTRIDE);
                ah[f][2] = ldb32(AsH + ab + 4);
                ah[f][3] = ldb32(AsH + ab + 8*ASTRIDE + 4);
                al[f][0] = ldb32(AsL + ab);
                al[f][1] = ldb32(AsL + ab + 8*ASTRIDE);
                al[f][2] = ldb32(AsL + ab + 4);
                al[f][3] = ldb32(AsL + ab + 8*ASTRIDE + 4);
            }
            #pragma unroll
            for (int g = 0; g < 4; g++) {
                int nn = wn*32 + g*8 + q;
                int bb = cur*BS_BUF + (k0+r)*BSTRIDE + nn;
                bh[g][0] = ldb32(BsH + bb);
                bh[g][1] = ldb32(BsH + bb + 4*BSTRIDE);
                bl[g][0] = ldb32(BsL + bb);
                bl[g][1] = ldb32(BsL + bb + 4*BSTRIDE);
            }
            #pragma unroll
            for (int f = 0; f < 2; f++)
                #pragma unroll
                for (int g = 0; g < 4; g++) {
                    mma_tf32(acc[f][g], ah[f], bh[g]);
                    mma_tf32(acc[f][g], ah[f], bl[g]);
                    mma_tf32(acc[f][g], al[f], bh[g]);
                }
        }

        if (t + 1 < nk) { stageA(nxt); stageB(nxt); }
        __syncthreads();
    }

    // epilogue: m16n8 frag: c0 (q, 2r), c1 (q, 2r+1), c2 (q+8, 2r), c3 (q+8, 2r+1)
    #pragma unroll
    for (int f = 0; f < 2; f++) {
        int row0 = bm + wm*32 + f*16 + q;
        #pragma unroll
        for (int g = 0; g < 4; g++) {
            int ncol = bn + wn*32 + g*8 + r*2;
            *(float2*)(C + (size_t)row0*N + ncol) =
                make_float2(acc[f][g][0], acc[f][g][1]);
            *(float2*)(C + (size_t)(row0+8)*N + ncol) =
                make_float2(acc[f][g][2], acc[f][g][3]);
        }
    }
}

// ---------------- GEMM wrappers ---------------------------------------------
// L1: Pl1[net*4+kp] = pooled @ W1[net] slice   grid(12,4,8) = 384
__global__ __launch_bounds__(256, 2) void k_l1(
    const float* __restrict__ pooled,
    const float* __restrict__ Wh1, const float* __restrict__ Wt1,
    float* __restrict__ Pl1)
{
    int z = blockIdx.z, net = z >> 2, kp = z & 3;
    gemm_core<0,0>(pooled, nullptr, nullptr, nullptr,
                   nullptr, nullptr, nullptr, D_,
                   net ? Wt1 : Wh1, H1_, H1_, 0,
                   Pl1 + (size_t)z*PL1_SLAB, H1_, kp*192, 192);
}

// L2: Pl2[net*8+kp] = relu(sum4 Pl1 + b1 + lb) @ W2[net]   grid(6,4,16) = 384
__global__ __launch_bounds__(256, 2) void k_l2(
    const float* __restrict__ Pl1,
    const float* __restrict__ Wh2, const float* __restrict__ Wt2,
    const float* __restrict__ bh1, const float* __restrict__ bt1,
    const int* __restrict__ labels,
    const float* __restrict__ eph, const float* __restrict__ ept,
    float* __restrict__ Pl2)
{
    int z = blockIdx.z, net = z >> 3, kp = z & 7;
    const float* base = Pl1 + (size_t)(net*4)*PL1_SLAB;
    gemm_core<1,0>(base, base + PL1_SLAB, base + 2*PL1_SLAB, base + 3*PL1_SLAB,
                   net ? bt1 : bh1, labels, net ? ept : eph, H1_,
                   net ? Wt2 : Wh2, H2_, H2_, 0,
                   Pl2 + (size_t)z*PL2_SLAB, H2_, kp*96, 96);
}

// u: Pu[kp] = head @ W_bil (segmented)   grid(12,4,4) = 192
__global__ __launch_bounds__(256, 2) void k_u(
    const float* __restrict__ head, const float* __restrict__ Wbil,
    float* __restrict__ Pu)
{
    int kp = blockIdx.z;
    gemm_core<0,0>(head, nullptr, nullptr, nullptr,
                   nullptr, nullptr, nullptr, H2_,
                   Wbil, H2_, H2_, H2_*H2_,
                   Pu + (size_t)kp*PU_SLAB, 2*H2_, kp*96, 96);
}

// V: Vp[bo*8+kp] = (sum4 Pu)[b,:,o-slice] @ tail_b^T   grid(4,2,32) = 256
__global__ __launch_bounds__(256, 2) void k_V(
    const float* __restrict__ Pu, const float* __restrict__ tail,
    float* __restrict__ Vp)
{
    int z = blockIdx.z, bo = z >> 3, kp = z & 7;
    int b = bo >> 1, o = bo & 1;
    const float* base = Pu + (size_t)(b*E_)*(2*H2_) + o*H2_;
    gemm_core<2,1>(base, base + PU_SLAB, base + 2*PU_SLAB, base + 3*PU_SLAB,
                   nullptr, nullptr, nullptr, 2*H2_,
                   tail + (size_t)b*E_*H2_, H2_, 0, 0,
                   Vp + (size_t)z*E_*E_, E_, kp*48, 48);
}

// ---------------- 1) span mean-pooling --------------------------------------
__global__ void pool_kernel(const float* __restrict__ hs,
                            const int* __restrict__ st,
                            const int* __restrict__ en) {
    int be = blockIdx.x;             // 0..511
    int b  = be >> 8;
    int s  = st[be];
    int len = en[be] - s;
    int cl  = len < 1 ? 1 : len;
    float inv = 1.0f / (float)cl;
    const float* base = hs + ((size_t)(b*T_ + s))*D_;
    for (int d = threadIdx.x; d < D_; d += blockDim.x) {
        float acc = 0.f;
        for (int t = 0; t < len; t++) acc += base[(size_t)t*D_ + d];
        g_pooled[(size_t)be*D_ + d] = acc * inv;
    }
}

// ---------------- 2) per-label projection through W1[768:] for BOTH nets ----
__global__ void labelproj2_kernel(const float* __restrict__ emb,
                                  const float* __restrict__ Wh1,
                                  const float* __restrict__ Wt1) {
    int gid = blockIdx.x*blockDim.x + threadIdx.x;  // 2*5*768 = 7680
    if (gid >= 2*NL_*H1_) return;
    int half = gid / (NL_*H1_);
    int r    = gid - half*(NL_*H1_);
    int l = r / H1_, n = r - l*H1_;
    const float* W1 = half ? Wt1 : Wh1;
    const float* wp = W1 + (size_t)D_*H1_ + n;      // rows 768..1535, col n
    const float* ep = emb + (size_t)l*D_;
    float acc = 0.f;
    #pragma unroll 4
    for (int k = 0; k < D_; k++) acc += ep[k] * wp[(size_t)k*H1_];
    if (half) g_ept[r] = acc; else g_eph[r] = acc;
}

// ---------------- combine L2: head/tail = relu(sum8 Pl2 + bias) -------------
__global__ void combine_l2(const float* __restrict__ Pl2,
                           const float* __restrict__ bh2,
                           const float* __restrict__ bt2,
                           float* __restrict__ head, float* __restrict__ tail)
{
    int idx = blockIdx.x*blockDim.x + threadIdx.x;
    int pq = ROWS_*H2_/4;
    if (idx >= 2*pq) return;
    int net = idx >= pq ? 1 : 0;
    int r = idx - net*pq;
    int col = (r*4) % H2_;
    const float* bs = net ? bt2 : bh2;
    float4 v = make_float4(bs[col], bs[col+1], bs[col+2], bs[col+3]);
    #pragma unroll
    for (int kp = 0; kp < 8; kp++) {
        float4 a = ((const float4*)(Pl2 + (size_t)(net*8+kp)*PL2_SLAB))[r];
        v.x += a.x; v.y += a.y; v.z += a.z; v.w += a.w;
    }
    v.x = fmaxf(v.x, 0.f); v.y = fmaxf(v.y, 0.f);
    v.z = fmaxf(v.z, 0.f); v.w = fmaxf(v.w, 0.f);
    (net ? (float4*)tail : (float4*)head)[r] = v;
}

// ---------------- combine V partials -> dense table -------------------------
__global__ void combine_V(const float* __restrict__ Vp, float* __restrict__ V) {
    int idx = blockIdx.x*blockDim.x + threadIdx.x;   // 4*65536/4 = 65536
    const int per = E_*E_/4;
    if (idx >= 4*per) return;
    int bo = idx / per, rr = idx - bo*per;
    float4 v = make_float4(0.f, 0.f, 0.f, 0.f);
    #pragma unroll
    for (int kp = 0; kp < 8; kp++) {
        float4 a = ((const float4*)(Vp + (size_t)(bo*8+kp)*E_*E_))[rr];
        v.x += a.x; v.y += a.y; v.z += a.z; v.w += a.w;
    }
    ((float4*)V)[idx] = v;
}

// ---------------- per-entity linear terms lh/lt -----------------------------
__global__ void lhlt_kernel(const float* __restrict__ Wlin) {
    int gid  = blockIdx.x*blockDim.x + threadIdx.x;
    int w    = gid >> 5;            // entity row 0..511
    int lane = gid & 31;
    if (w >= ROWS_) return;
    float s0=0.f, s1=0.f, s2=0.f, s3=0.f;
    for (int j = lane; j < H2_; j += 32) {
        float hv = g_head[(size_t)w*H2_ + j];
        float tv = g_tail[(size_t)w*H2_ + j];
        s0 += hv * Wlin[j*2+0];
        s1 += hv * Wlin[j*2+1];
        s2 += tv * Wlin[(H2_+j)*2+0];
        s3 += tv * Wlin[(H2_+j)*2+1];
    }
    #pragma unroll
    for (int off = 16; off > 0; off >>= 1) {
        s0 += __shfl_down_sync(0xffffffffu, s0, off);
        s1 += __shfl_down_sync(0xffffffffu, s1, off);
        s2 += __shfl_down_sync(0xffffffffu, s2, off);
        s3 += __shfl_down_sync(0xffffffffu, s3, off);
    }
    if (lane == 0) {
        g_lh[w*2+0] = s0; g_lh[w*2+1] = s1;
        g_lt[w*2+0] = s2; g_lt[w*2+1] = s3;
    }
}

// ---------------- final per-pair lookup -------------------------------------
__global__ void gather_kernel(const int* __restrict__ hidx,
                              const int* __restrict__ tidx,
                              const float* __restrict__ blin,
                              float* __restrict__ out) {
    int gid = blockIdx.x*blockDim.x + threadIdx.x;   // B*P = 131072
    if (gid >= B_*P_) return;
    int b = gid >> 16;
    int h = hidx[gid];
    int t = tidx[gid];
    int rh = (b << 8) + h;
    int rt = (b << 8) + t;
    size_t off = (size_t)(h << 8) + t;
    float v0 = g_V[((size_t)(b*2+0) << 16) + off];
    float v1 = g_V[((size_t)(b*2+1) << 16) + off];
    float2 r;
    r.x = v0 + g_lh[rh*2+0] + g_lt[rt*2+0] + blin[0];
    r.y = v1 + g_lh[rh*2+1] + g_lt[rt*2+1] + blin[1];
    ((float2*)out)[gid] = r;
}

// ---------------- launch ----------------------------------------------------
extern "C" void kernel_launch(void* const* d_in, const int* in_sizes, int n_in,
                              void* d_out, int out_size) {
    const float* hs   = (const float*)d_in[0];
    const float* emb  = (const float*)d_in[1];
    const float* Wh1  = (const float*)d_in[2];
    const float* bh1  = (const float*)d_in[3];
    const float* Wh2  = (const float*)d_in[4];
    const float* bh2  = (const float*)d_in[5];
    const float* Wt1  = (const float*)d_in[6];
    const float* bt1  = (const float*)d_in[7];
    const float* Wt2  = (const float*)d_in[8];
    const float* bt2  = (const float*)d_in[9];
    const float* Wbil = (const float*)d_in[10];
    const float* Wlin = (const float*)d_in[11];
    const float* blin = (const float*)d_in[12];
    const int*   est  = (const int*)d_in[13];
    const int*   een  = (const int*)d_in[14];
    const int*   elab = (const int*)d_in[15];
    const int*   hidx = (const int*)d_in[16];
    const int*   tidx = (const int*)d_in[17];

    float *p_pooled, *p_eph, *p_ept, *p_Pl1, *p_Pl2, *p_head, *p_tail,
          *p_Pu, *p_Vp, *p_V;
    cudaGetSymbolAddress((void**)&p_pooled, g_pooled);
    cudaGetSymbolAddress((void**)&p_eph,    g_eph);
    cudaGetSymbolAddress((void**)&p_ept,    g_ept);
    cudaGetSymbolAddress((void**)&p_Pl1,    g_Pl1);
    cudaGetSymbolAddress((void**)&p_Pl2,    g_Pl2);
    cudaGetSymbolAddress((void**)&p_head,   g_head);
    cudaGetSymbolAddress((void**)&p_tail,   g_tail);
    cudaGetSymbolAddress((void**)&p_Pu,     g_Pu);
    cudaGetSymbolAddress((void**)&p_Vp,     g_Vp);
    cudaGetSymbolAddress((void**)&p_V,      g_V);

    // allow >48KB dynamic smem on the GEMM kernels (non-stream API; capture-safe)
    cudaFuncSetAttribute(k_l1, cudaFuncAttributeMaxDynamicSharedMemorySize, SM_BYTES);
    cudaFuncSetAttribute(k_l2, cudaFuncAttributeMaxDynamicSharedMemorySize, SM_BYTES);
    cudaFuncSetAttribute(k_u,  cudaFuncAttributeMaxDynamicSharedMemorySize, SM_BYTES);
    cudaFuncSetAttribute(k_V,  cudaFuncAttributeMaxDynamicSharedMemorySize, SM_BYTES);

    // 1) span mean pooling -> g_pooled [512,768]
    pool_kernel<<<ROWS_, 256>>>(hs, est, een);

    // 2) label projections for BOTH nets in one launch
    labelproj2_kernel<<<(2*NL_*H1_ + 255)/256, 256>>>(emb, Wh1, Wt1);

    // 3) L1 partials (2 nets x split-K4): 384 blocks
    k_l1<<<dim3(H1_/64, ROWS_/128, 8), 256, SM_BYTES>>>(p_pooled, Wh1, Wt1, p_Pl1);

    // 4) L2 partials with fused L1-combine (2 nets x split-K8): 384 blocks
    k_l2<<<dim3(H2_/64, ROWS_/128, 16), 256, SM_BYTES>>>(
        p_Pl1, Wh2, Wt2, bh1, bt1, elab, p_eph, p_ept, p_Pl2);

    // 5) combine L2 partials -> head/tail
    combine_l2<<<(2*ROWS_*H2_/4 + 255)/256, 256>>>(p_Pl2, bh2, bt2, p_head, p_tail);

    // 6) per-entity linear terms
    lhlt_kernel<<<(ROWS_*32 + 255)/256, 256>>>(Wlin);

    // 7) u partials = head @ W_bil (segmented-B), split-K4: 192 blocks
    k_u<<<dim3((2*H2_)/64, ROWS_/128, 4), 256, SM_BYTES>>>(p_head, Wbil, p_Pu);

    // 8) V partials = (sum4 Pu) @ tail^T, per (b,o) x split-K8: 256 blocks
    k_V<<<dim3(E_/64, E_/128, 32), 256, SM_BYTES>>>(p_Pu, p_tail, p_Vp);

    // 9) combine V partials -> dense table
    combine_V<<<(4*E_*E_/4 + 255)/256, 256>>>(p_Vp, p_V);

    // 10) per-pair lookup + linear terms + bias
    gather_kernel<<<(B_*P_ + 255)/256, 256>>>(hidx, tidx, blin, (float*)d_out);
}

// round 11
// speedup vs baseline: 1.4345x; 1.1736x over previous
#include <cuda_runtime.h>
#include <cuda_fp16.h>
#include <cstdint>

// Problem constants (fixed by the reference)
#define B_    2
#define T_    512
#define D_    768
#define E_    256
#define P_    65536
#define H1_   768
#define H2_   384
#define NL_   5
#define ROWS_ (B_*E_)          // 512 fused (b,e) rows

#define PL1_SLAB (ROWS_*H1_)   // 393216
#define PL2_SLAB (ROWS_*H2_)   // 196608
#define PU_SLAB  (ROWS_*2*H2_) // 393216

// ---------------- scratch (static device globals; no allocation) ------------
__device__ float g_pooled[ROWS_*D_];        // mean-pooled spans       [512,768]
__device__ float g_eph[NL_*H1_];            // emb @ Wh1[768:]         [5,768]
__device__ float g_ept[NL_*H1_];            // emb @ Wt1[768:]         [5,768]
__device__ float g_Pl1[4*PL1_SLAB];         // L1 partials [net*2+kp]
__device__ float g_Pl2[8*PL2_SLAB];         // L2 partials [net*4+kp]
__device__ float g_head[ROWS_*H2_];         // head_all                [512,384]
__device__ float g_tail[ROWS_*H2_];         // tail_all                [512,384]
__device__ float g_Pu[4*PU_SLAB];           // u partials [kp]
__device__ float g_Vp[16*E_*E_];            // V partials [bo*4+kp][256*256]
__device__ float g_lh[ROWS_*2];             // head @ W_lin[:384]
__device__ float g_lt[ROWS_*2];             // tail @ W_lin[384:]

// ---------------- fp16 helpers ----------------------------------------------
__device__ __forceinline__ void mma_f16(float c[4],
                                        const uint32_t a[4],
                                        const uint32_t b[2]) {
    asm volatile(
        "mma.sync.aligned.m16n8k16.row.col.f32.f16.f16.f32 "
        "{%0,%1,%2,%3}, {%4,%5,%6,%7}, {%8,%9}, {%0,%1,%2,%3};"
        : "+f"(c[0]), "+f"(c[1]), "+f"(c[2]), "+f"(c[3])
        : "r"(a[0]), "r"(a[1]), "r"(a[2]), "r"(a[3]), "r"(b[0]), "r"(b[1]));
}
__device__ __forceinline__ uint32_t pk2(__half a, __half b) {
    __half2 t = __halves2half2(a, b);
    return *reinterpret_cast<uint32_t*>(&t);
}
// split pair (x0,x1) -> hi word + lo word (fp16 hi/lo decomposition)
__device__ __forceinline__ void hsplit2(float x0, float x1,
                                        uint32_t& hi, uint32_t& lo) {
    __half h0 = __float2half_rn(x0), h1 = __float2half_rn(x1);
    float l0 = x0 - __half2float(h0);
    float l1 = x1 - __half2float(h1);
    hi = pk2(h0, h1);
    lo = pk2(__float2half_rn(l0), __float2half_rn(l1));
}

// smem layout (uint32 words, each = half2 k-pair):
// A: 128 rows x stride 20 words.  Row: words 0..3 = hi k-pairs 0..3,
//    words 4..7 = hi k-pairs 4..7, words 8..15 = lo (same order +8).
// B: 64 n-rows x stride 20 words, same hi/lo split.
// Frag loads: word = row*20 + r (+4 for k+8 chunk, +8 for lo);
//   banks (20q + r + c) mod 32 distinct across the warp -> conflict-free.
#define AW      20
#define A_BUF_W (128*AW)   // 2560
#define B_BUF_W (64*AW)    // 1280
#define SM_WORDS (2*A_BUF_W + 2*B_BUF_W)  // 7680 words = 30 KB

// ---------------- 2xfp16-split GEMM core (hh+hl+lh, fp32 accum) -------------
// Block tile 128(M) x 64(N), BK=16 (one m16n8k16 step), 256 threads = 8 warps
// (4 m-warps x 2 n-warps), warp tile 32x32 (2 m-frags x 4 n-frags).
// AMODE: 0 = plain A0.
//        1 = relu(A0 + A1 + abias[k] + albias[labels[row]][k])
//        2 = A0 + A1 + A2 + A3 (sum of 4 split-K partials)
// BMODE: 0 = NN, B[k][n] at W + (n/segw)*segstride + k*ldb + (n%segw)
//        1 = NT, B[n][k] at W + n*ldb + k
// M%128==0, N%64==0, segw%64==0, kslice%16==0.
template<int AMODE, int BMODE>
__device__ __forceinline__ void gemm_core(
    const float* __restrict__ A0, const float* __restrict__ A1,
    const float* __restrict__ A2, const float* __restrict__ A3,
    const float* __restrict__ abias, const int* __restrict__ labels,
    const float* __restrict__ albias, int lda,
    const float* __restrict__ W, int ldb, int segw, int segstride,
    float* __restrict__ C, int N, int kstart, int kslice)
{
    __shared__ uint32_t smw[SM_WORDS];
    uint32_t* As = smw;                 // 2 bufs x A_BUF_W
    uint32_t* Bs = smw + 2*A_BUF_W;     // 2 bufs x B_BUF_W

    const int tid = threadIdx.x;
    const int bm = blockIdx.y * 128, bn = blockIdx.x * 64;
    const int lane = tid & 31, wid = tid >> 5;
    const int wm = wid & 3, wn = wid >> 2;     // 4 x 2 warp grid
    const int q = lane >> 2, r = lane & 3;

    // ---- A staging map: row = tid>>1, k-half = (tid&1)*8 ----
    const int arow = tid >> 1, ac8 = (tid & 1) * 8;
    const float* Ap0 = A0 + (size_t)(bm+arow)*lda + kstart + ac8;
    const float* Ap1 = (AMODE>=1) ? A1 + (size_t)(bm+arow)*lda + kstart + ac8 : nullptr;
    const float* Ap2 = (AMODE==2) ? A2 + (size_t)(bm+arow)*lda + kstart + ac8 : nullptr;
    const float* Ap3 = (AMODE==2) ? A3 + (size_t)(bm+arow)*lda + kstart + ac8 : nullptr;
    const float* biasp = (AMODE==1) ? abias + kstart + ac8 : nullptr;
    const float* lbp   = (AMODE==1)
        ? albias + (size_t)labels[bm+arow]*lda + kstart + ac8 : nullptr;

    // ---- B staging map ----
    // NN: thread -> k-pair kk=tid&7, n-pair npair=tid>>3 (n0=2*npair)
    // NT: thread -> n-row nrow=tid>>2, k-quad kq=tid&3
    const float* gB0 = nullptr; const float* gB1 = nullptr;
    int b_kk = 0, b_n0 = 0, b_nrow = 0, b_kq = 0;
    if (BMODE == 0) {
        b_kk = tid & 7;  int npair = tid >> 3;  b_n0 = 2*npair;
        int seg = bn / segw;
        const float* baseW = W + (size_t)seg*segstride + (bn - seg*segw) + b_n0;
        gB0 = baseW + (size_t)(kstart + 2*b_kk)*ldb;
        gB1 = gB0 + ldb;
    } else {
        b_nrow = tid >> 2;  b_kq = tid & 3;
        gB0 = W + (size_t)(bn + b_nrow)*ldb + kstart + b_kq*4;
    }

    float va[8], vb[4];

    auto fetchA = [&](int t) {
        const float* p = Ap0 + t*16;
        float4 x0 = *(const float4*)p, x1 = *(const float4*)(p+4);
        va[0]=x0.x; va[1]=x0.y; va[2]=x0.z; va[3]=x0.w;
        va[4]=x1.x; va[5]=x1.y; va[6]=x1.z; va[7]=x1.w;
        if (AMODE >= 1) {
            const float* p1 = Ap1 + t*16;
            float4 y0 = *(const float4*)p1, y1 = *(const float4*)(p1+4);
            va[0]+=y0.x; va[1]+=y0.y; va[2]+=y0.z; va[3]+=y0.w;
            va[4]+=y1.x; va[5]+=y1.y; va[6]+=y1.z; va[7]+=y1.w;
        }
        if (AMODE == 2) {
            const float* p2 = Ap2 + t*16;
            const float* p3 = Ap3 + t*16;
            float4 y0 = *(const float4*)p2, y1 = *(const float4*)(p2+4);
            float4 z0 = *(const float4*)p3, z1 = *(const float4*)(p3+4);
            va[0]+=y0.x+z0.x; va[1]+=y0.y+z0.y; va[2]+=y0.z+z0.z; va[3]+=y0.w+z0.w;
            va[4]+=y1.x+z1.x; va[5]+=y1.y+z1.y; va[6]+=y1.z+z1.z; va[7]+=y1.w+z1.w;
        }
        if (AMODE == 1) {
            float4 b0 = *(const float4*)(biasp + t*16), b1 = *(const float4*)(biasp + t*16 + 4);
            float4 l0 = *(const float4*)(lbp + t*16),   l1 = *(const float4*)(lbp + t*16 + 4);
            va[0] = fmaxf(va[0] + b0.x + l0.x, 0.f);
            va[1] = fmaxf(va[1] + b0.y + l0.y, 0.f);
            va[2] = fmaxf(va[2] + b0.z + l0.z, 0.f);
            va[3] = fmaxf(va[3] + b0.w + l0.w, 0.f);
            va[4] = fmaxf(va[4] + b1.x + l1.x, 0.f);
            va[5] = fmaxf(va[5] + b1.y + l1.y, 0.f);
            va[6] = fmaxf(va[6] + b1.z + l1.z, 0.f);
            va[7] = fmaxf(va[7] + b1.w + l1.w, 0.f);
        }
    };
    auto fetchB = [&](int t) {
        if (BMODE == 0) {
            float2 x = *(const float2*)(gB0 + (size_t)t*16*ldb);
            float2 y = *(const float2*)(gB1 + (size_t)t*16*ldb);
            vb[0]=x.x; vb[1]=x.y; vb[2]=y.x; vb[3]=y.y;   // B[k0][n0,n1], B[k1][n0,n1]
        } else {
            float4 x = *(const float4*)(gB0 + t*16);
            vb[0]=x.x; vb[1]=x.y; vb[2]=x.z; vb[3]=x.w;   // B[n][k..k+3]
        }
    };
    auto stageA = [&](int buf) {
        int base = buf*A_BUF_W + arow*AW + (tid&1)*4;
        #pragma unroll
        for (int j = 0; j < 4; j++) {
            uint32_t hi, lo;
            hsplit2(va[2*j], va[2*j+1], hi, lo);
            As[base + j]     = hi;
            As[base + 8 + j] = lo;
        }
    };
    auto stageB = [&](int buf) {
        if (BMODE == 0) {
            // column n0: half2(B[k0][n0], B[k1][n0]); column n1 likewise
            uint32_t hi, lo;
            hsplit2(vb[0], vb[2], hi, lo);
            Bs[buf*B_BUF_W + b_n0*AW + b_kk]     = hi;
            Bs[buf*B_BUF_W + b_n0*AW + b_kk + 8] = lo;
            hsplit2(vb[1], vb[3], hi, lo);
            Bs[buf*B_BUF_W + (b_n0+1)*AW + b_kk]     = hi;
            Bs[buf*B_BUF_W + (b_n0+1)*AW + b_kk + 8] = lo;
        } else {
            int base = buf*B_BUF_W + b_nrow*AW + b_kq*2;
            uint32_t hi, lo;
            hsplit2(vb[0], vb[1], hi, lo);
            Bs[base]     = hi;  Bs[base + 8]  = lo;
            hsplit2(vb[2], vb[3], hi, lo);
            Bs[base + 1] = hi;  Bs[base + 9]  = lo;
        }
    };

    float acc[2][4][4];
    #pragma unroll
    for (int f = 0; f < 2; f++)
        #pragma unroll
        for (int g = 0; g < 4; g++)
            #pragma unroll
            for (int i = 0; i < 4; i++) acc[f][g][i] = 0.f;

    fetchA(0); fetchB(0);
    stageA(0); stageB(0);
    __syncthreads();

    const int nk = kslice >> 4;
    for (int t = 0; t < nk; t++) {
        int cur = t & 1, nxt = cur ^ 1;
        if (t + 1 < nk) { fetchA(t+1); fetchB(t+1); }

        // ---- one m16n8k16 step per buffer ----
        {
            uint32_t ah[2][4], al[2][4];
            #pragma unroll
            for (int f = 0; f < 2; f++) {
                int m0 = wm*32 + f*16 + q;
                int w0 = cur*A_BUF_W + m0*AW + r;
                int w1 = cur*A_BUF_W + (m0+8)*AW + r;
                ah[f][0] = As[w0];     ah[f][1] = As[w1];
                ah[f][2] = As[w0+4];   ah[f][3] = As[w1+4];
                al[f][0] = As[w0+8];   al[f][1] = As[w1+8];
                al[f][2] = As[w0+12];  al[f][3] = As[w1+12];
            }
            #pragma unroll
            for (int g = 0; g < 4; g++) {
                int nn = wn*32 + g*8 + q;
                int wb = cur*B_BUF_W + nn*AW + r;
                uint32_t bh[2] = {Bs[wb],   Bs[wb+4]};
                uint32_t bl[2] = {Bs[wb+8], Bs[wb+12]};
                #pragma unroll
                for (int f = 0; f < 2; f++) {
                    mma_f16(acc[f][g], ah[f], bh);
                    mma_f16(acc[f][g], ah[f], bl);
                    mma_f16(acc[f][g], al[f], bh);
                }
            }
        }

        if (t + 1 < nk) { stageA(nxt); stageB(nxt); }
        __syncthreads();
    }

    // epilogue: m16n8 frag: c0 (q,2r), c1 (q,2r+1), c2 (q+8,2r), c3 (q+8,2r+1)
    #pragma unroll
    for (int f = 0; f < 2; f++) {
        int row0 = bm + wm*32 + f*16 + q;
        #pragma unroll
        for (int g = 0; g < 4; g++) {
            int ncol = bn + wn*32 + g*8 + r*2;
            *(float2*)(C + (size_t)row0*N + ncol) =
                make_float2(acc[f][g][0], acc[f][g][1]);
            *(float2*)(C + (size_t)(row0+8)*N + ncol) =
                make_float2(acc[f][g][2], acc[f][g][3]);
        }
    }
}

// ---------------- GEMM wrappers (R8 split config) ----------------------------
// L1: Pl1[net*2+kp] = pooled @ W1[net] slice   grid(12,4,4) = 192
__global__ __launch_bounds__(256, 2) void k_l1(
    const float* __restrict__ pooled,
    const float* __restrict__ Wh1, const float* __restrict__ Wt1,
    float* __restrict__ Pl1)
{
    int z = blockIdx.z, net = z >> 1, kp = z & 1;
    gemm_core<0,0>(pooled, nullptr, nullptr, nullptr,
                   nullptr, nullptr, nullptr, D_,
                   net ? Wt1 : Wh1, H1_, H1_, 0,
                   Pl1 + (size_t)z*PL1_SLAB, H1_, kp*384, 384);
}

// L2: Pl2[net*4+kp] = relu(Pl1sum2 + b1 + lb) @ W2[net]   grid(6,4,8) = 192
__global__ __launch_bounds__(256, 2) void k_l2(
    const float* __restrict__ Pl1,
    const float* __restrict__ Wh2, const float* __restrict__ Wt2,
    const float* __restrict__ bh1, const float* __restrict__ bt1,
    const int* __restrict__ labels,
    const float* __restrict__ eph, const float* __restrict__ ept,
    float* __restrict__ Pl2)
{
    int z = blockIdx.z, net = z >> 2, kp = z & 3;
    const float* base = Pl1 + (size_t)(net*2)*PL1_SLAB;
    gemm_core<1,0>(base, base + PL1_SLAB, nullptr, nullptr,
                   net ? bt1 : bh1, labels, net ? ept : eph, H1_,
                   net ? Wt2 : Wh2, H2_, H2_, 0,
                   Pl2 + (size_t)z*PL2_SLAB, H2_, kp*192, 192);
}

// u: Pu[kp] = head @ W_bil (segmented)   grid(12,4,4) = 192
__global__ __launch_bounds__(256, 2) void k_u(
    const float* __restrict__ head, const float* __restrict__ Wbil,
    float* __restrict__ Pu)
{
    int kp = blockIdx.z;
    gemm_core<0,0>(head, nullptr, nullptr, nullptr,
                   nullptr, nullptr, nullptr, H2_,
                   Wbil, H2_, H2_, H2_*H2_,
                   Pu + (size_t)kp*PU_SLAB, 2*H2_, kp*96, 96);
}

// V: Vp[bo*4+kp] = (sum4 Pu)[b,:,o-slice] @ tail_b^T   grid(4,2,16) = 128
__global__ __launch_bounds__(256, 2) void k_V(
    const float* __restrict__ Pu, const float* __restrict__ tail,
    float* __restrict__ Vp)
{
    int z = blockIdx.z, bo = z >> 2, kp = z & 3;
    int b = bo >> 1, o = bo & 1;
    const float* base = Pu + (size_t)(b*E_)*(2*H2_) + o*H2_;
    gemm_core<2,1>(base, base + PU_SLAB, base + 2*PU_SLAB, base + 3*PU_SLAB,
                   nullptr, nullptr, nullptr, 2*H2_,
                   tail + (size_t)b*E_*H2_, H2_, 0, 0,
                   Vp + (size_t)z*E_*E_, E_, kp*96, 96);
}

// ---------------- 1) span mean-pooling --------------------------------------
__global__ void pool_kernel(const float* __restrict__ hs,
                            const int* __restrict__ st,
                            const int* __restrict__ en) {
    int be = blockIdx.x;             // 0..511
    int b  = be >> 8;
    int s  = st[be];
    int len = en[be] - s;
    int cl  = len < 1 ? 1 : len;
    float inv = 1.0f / (float)cl;
    const float* base = hs + ((size_t)(b*T_ + s))*D_;
    for (int d = threadIdx.x; d < D_; d += blockDim.x) {
        float acc = 0.f;
        for (int t = 0; t < len; t++) acc += base[(size_t)t*D_ + d];
        g_pooled[(size_t)be*D_ + d] = acc * inv;
    }
}

// ---------------- 2) per-label projection through W1[768:] for BOTH nets ----
__global__ void labelproj2_kernel(const float* __restrict__ emb,
                                  const float* __restrict__ Wh1,
                                  const float* __restrict__ Wt1) {
    int gid = blockIdx.x*blockDim.x + threadIdx.x;  // 2*5*768 = 7680
    if (gid >= 2*NL_*H1_) return;
    int half = gid / (NL_*H1_);
    int r    = gid - half*(NL_*H1_);
    int l = r / H1_, n = r - l*H1_;
    const float* W1 = half ? Wt1 : Wh1;
    const float* wp = W1 + (size_t)D_*H1_ + n;      // rows 768..1535, col n
    const float* ep = emb + (size_t)l*D_;
    float acc = 0.f;
    #pragma unroll 4
    for (int k = 0; k < D_; k++) acc += ep[k] * wp[(size_t)k*H1_];
    if (half) g_ept[r] = acc; else g_eph[r] = acc;
}

// ---------------- combine L2: head/tail = relu(sum4 Pl2 + bias) -------------
__global__ void combine_l2(const float* __restrict__ Pl2,
                           const float* __restrict__ bh2,
                           const float* __restrict__ bt2,
                           float* __restrict__ head, float* __restrict__ tail)
{
    int idx = blockIdx.x*blockDim.x + threadIdx.x;
    int pq = ROWS_*H2_/4;
    if (idx >= 2*pq) return;
    int net = idx >= pq ? 1 : 0;
    int r = idx - net*pq;
    int col = (r*4) % H2_;
    const float* bs = net ? bt2 : bh2;
    float4 v = make_float4(bs[col], bs[col+1], bs[col+2], bs[col+3]);
    #pragma unroll
    for (int kp = 0; kp < 4; kp++) {
        float4 a = ((const float4*)(Pl2 + (size_t)(net*4+kp)*PL2_SLAB))[r];
        v.x += a.x; v.y += a.y; v.z += a.z; v.w += a.w;
    }
    v.x = fmaxf(v.x, 0.f); v.y = fmaxf(v.y, 0.f);
    v.z = fmaxf(v.z, 0.f); v.w = fmaxf(v.w, 0.f);
    (net ? (float4*)tail : (float4*)head)[r] = v;
}

// ---------------- per-entity linear terms lh/lt -----------------------------
__global__ void lhlt_kernel(const float* __restrict__ Wlin) {
    int gid  = blockIdx.x*blockDim.x + threadIdx.x;
    int w    = gid >> 5;            // entity row 0..511
    int lane = gid & 31;
    if (w >= ROWS_) return;
    float s0=0.f, s1=0.f, s2=0.f, s3=0.f;
    for (int j = lane; j < H2_; j += 32) {
        float hv = g_head[(size_t)w*H2_ + j];
        float tv = g_tail[(size_t)w*H2_ + j];
        s0 += hv * Wlin[j*2+0];
        s1 += hv * Wlin[j*2+1];
        s2 += tv * Wlin[(H2_+j)*2+0];
        s3 += tv * Wlin[(H2_+j)*2+1];
    }
    #pragma unroll
    for (int off = 16; off > 0; off >>= 1) {
        s0 += __shfl_down_sync(0xffffffffu, s0, off);
        s1 += __shfl_down_sync(0xffffffffu, s1, off);
        s2 += __shfl_down_sync(0xffffffffu, s2, off);
        s3 += __shfl_down_sync(0xffffffffu, s3, off);
    }
    if (lane == 0) {
        g_lh[w*2+0] = s0; g_lh[w*2+1] = s1;
        g_lt[w*2+0] = s2; g_lt[w*2+1] = s3;
    }
}

// ---------------- final per-pair lookup (sums 4 V partials per o) -----------
__global__ void gather_kernel(const int* __restrict__ hidx,
                              const int* __restrict__ tidx,
                              const float* __restrict__ blin,
                              float* __restrict__ out) {
    int gid = blockIdx.x*blockDim.x + threadIdx.x;   // B*P = 131072
    if (gid >= B_*P_) return;
    int b = gid >> 16;
    int h = hidx[gid];
    int t = tidx[gid];
    int rh = (b << 8) + h;
    int rt = (b << 8) + t;
    size_t off = (size_t)(h << 8) + t;
    float v0 = 0.f, v1 = 0.f;
    #pragma unroll
    for (int kp = 0; kp < 4; kp++) {
        v0 += g_Vp[(((size_t)(b*2+0)*4 + kp) << 16) + off];
        v1 += g_Vp[(((size_t)(b*2+1)*4 + kp) << 16) + off];
    }
    float2 r;
    r.x = v0 + g_lh[rh*2+0] + g_lt[rt*2+0] + blin[0];
    r.y = v1 + g_lh[rh*2+1] + g_lt[rt*2+1] + blin[1];
    ((float2*)out)[gid] = r;
}

// ---------------- launch ----------------------------------------------------
extern "C" void kernel_launch(void* const* d_in, const int* in_sizes, int n_in,
                              void* d_out, int out_size) {
    const float* hs   = (const float*)d_in[0];
    const float* emb  = (const float*)d_in[1];
    const float* Wh1  = (const float*)d_in[2];
    const float* bh1  = (const float*)d_in[3];
    const float* Wh2  = (const float*)d_in[4];
    const float* bh2  = (const float*)d_in[5];
    const float* Wt1  = (const float*)d_in[6];
    const float* bt1  = (const float*)d_in[7];
    const float* Wt2  = (const float*)d_in[8];
    const float* bt2  = (const float*)d_in[9];
    const float* Wbil = (const float*)d_in[10];
    const float* Wlin = (const float*)d_in[11];
    const float* blin = (const float*)d_in[12];
    const int*   est  = (const int*)d_in[13];
    const int*   een  = (const int*)d_in[14];
    const int*   elab = (const int*)d_in[15];
    const int*   hidx = (const int*)d_in[16];
    const int*   tidx = (const int*)d_in[17];

    float *p_pooled, *p_eph, *p_ept, *p_Pl1, *p_Pl2, *p_head, *p_tail,
          *p_Pu, *p_Vp;
    cudaGetSymbolAddress((void**)&p_pooled, g_pooled);
    cudaGetSymbolAddress((void**)&p_eph,    g_eph);
    cudaGetSymbolAddress((void**)&p_ept,    g_ept);
    cudaGetSymbolAddress((void**)&p_Pl1,    g_Pl1);
    cudaGetSymbolAddress((void**)&p_Pl2,    g_Pl2);
    cudaGetSymbolAddress((void**)&p_head,   g_head);
    cudaGetSymbolAddress((void**)&p_tail,   g_tail);
    cudaGetSymbolAddress((void**)&p_Pu,     g_Pu);
    cudaGetSymbolAddress((void**)&p_Vp,     g_Vp);

    // 1) span mean pooling -> g_pooled [512,768]
    pool_kernel<<<ROWS_, 256>>>(hs, est, een);

    // 2) label projections for BOTH nets in one launch
    labelproj2_kernel<<<(2*NL_*H1_ + 255)/256, 256>>>(emb, Wh1, Wt1);

    // 3) L1 partials (2 nets x split-K2): 192 blocks
    k_l1<<<dim3(H1_/64, ROWS_/128, 4), 256>>>(p_pooled, Wh1, Wt1, p_Pl1);

    // 4) L2 partials with fused L1-combine (2 nets x split-K4): 192 blocks
    k_l2<<<dim3(H2_/64, ROWS_/128, 8), 256>>>(
        p_Pl1, Wh2, Wt2, bh1, bt1, elab, p_eph, p_ept, p_Pl2);

    // 5) combine L2 partials -> head/tail
    combine_l2<<<(2*ROWS_*H2_/4 + 255)/256, 256>>>(p_Pl2, bh2, bt2, p_head, p_tail);

    // 6) per-entity linear terms
    lhlt_kernel<<<(ROWS_*32 + 255)/256, 256>>>(Wlin);

    // 7) u partials = head @ W_bil (segmented-B), split-K4: 192 blocks
    k_u<<<dim3((2*H2_)/64, ROWS_/128, 4), 256>>>(p_head, Wbil, p_Pu);

    // 8) V partials = (sum4 Pu) @ tail^T, per (b,o) x split-K4: 128 blocks
    k_V<<<dim3(E_/64, E_/128, 16), 256>>>(p_Pu, p_tail, p_Vp);

    // 9) per-pair lookup (sums V partials) + linear terms + bias
    gather_kernel<<<(B_*P_ + 255)/256, 256>>>(hidx, tidx, blin, (float*)d_out);
}

// round 12
// speedup vs baseline: 1.4769x; 1.0296x over previous
#include <cuda_runtime.h>
#include <cuda_fp16.h>
#include <cstdint>

// Problem constants (fixed by the reference)
#define B_    2
#define T_    512
#define D_    768
#define E_    256
#define P_    65536
#define H1_   768
#define H2_   384
#define NL_   5
#define ROWS_ (B_*E_)          // 512 fused (b,e) rows

#define PL1_SLAB (ROWS_*H1_)   // 393216
#define PL2_SLAB (ROWS_*H2_)   // 196608
#define PU_SLAB  (ROWS_*2*H2_) // 393216

// ---------------- scratch (static device globals; no allocation) ------------
__device__ float g_pooled[ROWS_*D_];        // mean-pooled spans       [512,768]
__device__ float g_eph[NL_*H1_];            // emb @ Wh1[768:]         [5,768]
__device__ float g_ept[NL_*H1_];            // emb @ Wt1[768:]         [5,768]
__device__ float g_Pl1[4*PL1_SLAB];         // L1 partials [net*2+kp]
__device__ float g_Pl2[8*PL2_SLAB];         // L2 partials [net*4+kp]
__device__ float g_head[ROWS_*H2_];         // head_all                [512,384]
__device__ float g_tail[ROWS_*H2_];         // tail_all                [512,384]
__device__ float g_Pu[4*PU_SLAB];           // u partials [kp]
__device__ float g_Vp[16*E_*E_];            // V partials [bo*4+kp][256*256]
__device__ float g_lh[ROWS_*2];             // head @ W_lin[:384]
__device__ float g_lt[ROWS_*2];             // tail @ W_lin[384:]

// ---------------- fp16 helpers ----------------------------------------------
__device__ __forceinline__ void mma_f16(float c[4],
                                        const uint32_t a[4],
                                        const uint32_t b[2]) {
    asm volatile(
        "mma.sync.aligned.m16n8k16.row.col.f32.f16.f16.f32 "
        "{%0,%1,%2,%3}, {%4,%5,%6,%7}, {%8,%9}, {%0,%1,%2,%3};"
        : "+f"(c[0]), "+f"(c[1]), "+f"(c[2]), "+f"(c[3])
        : "r"(a[0]), "r"(a[1]), "r"(a[2]), "r"(a[3]), "r"(b[0]), "r"(b[1]));
}
__device__ __forceinline__ uint32_t pk2(__half a, __half b) {
    __half2 t = __halves2half2(a, b);
    return *reinterpret_cast<uint32_t*>(&t);
}
// split pair (x0,x1) -> hi word + lo word (fp16 hi/lo decomposition)
__device__ __forceinline__ void hsplit2(float x0, float x1,
                                        uint32_t& hi, uint32_t& lo) {
    __half h0 = __float2half_rn(x0), h1 = __float2half_rn(x1);
    float l0 = x0 - __half2float(h0);
    float l1 = x1 - __half2float(h1);
    hi = pk2(h0, h1);
    lo = pk2(__float2half_rn(l0), __float2half_rn(l1));
}

// smem layout (uint32 words, each = half2 k-pair).  BK = 32.
// A: 128 rows x stride 36 words.  Row: words 0..15 = hi k-pairs 0..15,
//    words 16..31 = lo (same order).  B: 64 n-rows x stride 36, same split.
// Frag loads (step s, k-offset 16s): word = row*36 + s*8 + r (+4 for k+8,
//   +16 for lo); banks (36q + r + c) mod 32 = (4q + r + c) distinct. CF.
#define AW2      36
#define A_BUF_W  (128*AW2)   // 4608
#define B_BUF_W  (64*AW2)    // 2304
#define SM_WORDS (2*A_BUF_W + 2*B_BUF_W)  // 13824 words = 55296 B
#define SM_BYTES (SM_WORDS*4)

// ---------------- 2xfp16-split GEMM core (hh+hl+lh, fp32 accum), BK=32 ------
// Block tile 128(M) x 64(N), BK=32 (two m16n8k16 steps per buffer),
// 256 threads = 8 warps (4 m x 2 n), warp tile 32x32.
// AMODE: 0 plain A0; 1 relu(A0+A1 + abias[k] + albias[labels[row]][k]);
//        2 A0+A1+A2+A3.
// BMODE: 0 NN  B[k][n] at W + (n/segw)*segstride + k*ldb + (n%segw)
//        1 NT  B[n][k] at W + n*ldb + k
// M%128==0, N%64==0, segw%64==0, kslice%32==0.
template<int AMODE, int BMODE>
__device__ __forceinline__ void gemm_core(
    const float* __restrict__ A0, const float* __restrict__ A1,
    const float* __restrict__ A2, const float* __restrict__ A3,
    const float* __restrict__ abias, const int* __restrict__ labels,
    const float* __restrict__ albias, int lda,
    const float* __restrict__ W, int ldb, int segw, int segstride,
    float* __restrict__ C, int N, int kstart, int kslice)
{
    extern __shared__ uint32_t smw[];
    uint32_t* As = smw;                 // 2 bufs x A_BUF_W
    uint32_t* Bs = smw + 2*A_BUF_W;     // 2 bufs x B_BUF_W

    const int tid = threadIdx.x;
    const int bm = blockIdx.y * 128, bn = blockIdx.x * 64;
    const int lane = tid & 31, wid = tid >> 5;
    const int wm = wid & 3, wn = wid >> 2;     // 4 x 2 warp grid
    const int q = lane >> 2, r = lane & 3;

    // ---- A staging map: row = tid>>1, k-half = (tid&1)*16 ----
    const int arow = tid >> 1, ah16 = (tid & 1);
    const float* Ap0 = A0 + (size_t)(bm+arow)*lda + kstart + ah16*16;
    const float* Ap1 = (AMODE>=1) ? A1 + (size_t)(bm+arow)*lda + kstart + ah16*16 : nullptr;
    const float* Ap2 = (AMODE==2) ? A2 + (size_t)(bm+arow)*lda + kstart + ah16*16 : nullptr;
    const float* Ap3 = (AMODE==2) ? A3 + (size_t)(bm+arow)*lda + kstart + ah16*16 : nullptr;
    const float* biasp = (AMODE==1) ? abias + kstart + ah16*16 : nullptr;
    const float* lbp   = (AMODE==1)
        ? albias + (size_t)labels[bm+arow]*lda + kstart + ah16*16 : nullptr;

    // ---- B staging map ----
    // NN: j = tid&7 -> kpairs 2j,2j+1 (k rows 4j..4j+3); npair = tid>>3 -> n0=2*npair
    // NT: nrow = tid>>2, kq = tid&3 -> k-offset kq*8 (4 kpairs)
    const float* gB = nullptr;
    int b_j = 0, b_n0 = 0, b_nrow = 0, b_kq = 0;
    if (BMODE == 0) {
        b_j = tid & 7;  int npair = tid >> 3;  b_n0 = 2*npair;
        int seg = bn / segw;
        gB = W + (size_t)seg*segstride + (bn - seg*segw) + b_n0
               + (size_t)(kstart + 4*b_j)*ldb;
    } else {
        b_nrow = tid >> 2;  b_kq = tid & 3;
        gB = W + (size_t)(bn + b_nrow)*ldb + kstart + b_kq*8;
    }

    float va[16], vb[8];

    auto fetchA = [&](int t) {
        const float4* p = (const float4*)(Ap0 + t*32);
        #pragma unroll
        for (int j = 0; j < 4; j++) {
            float4 x = p[j];
            va[4*j]=x.x; va[4*j+1]=x.y; va[4*j+2]=x.z; va[4*j+3]=x.w;
        }
        if (AMODE >= 1) {
            const float4* p1 = (const float4*)(Ap1 + t*32);
            #pragma unroll
            for (int j = 0; j < 4; j++) {
                float4 y = p1[j];
                va[4*j]+=y.x; va[4*j+1]+=y.y; va[4*j+2]+=y.z; va[4*j+3]+=y.w;
            }
        }
        if (AMODE == 2) {
            const float4* p2 = (const float4*)(Ap2 + t*32);
            const float4* p3 = (const float4*)(Ap3 + t*32);
            #pragma unroll
            for (int j = 0; j < 4; j++) {
                float4 y = p2[j], z = p3[j];
                va[4*j]  += y.x + z.x; va[4*j+1]+= y.y + z.y;
                va[4*j+2]+= y.z + z.z; va[4*j+3]+= y.w + z.w;
            }
        }
        if (AMODE == 1) {
            const float4* pb = (const float4*)(biasp + t*32);
            const float4* pl = (const float4*)(lbp + t*32);
            #pragma unroll
            for (int j = 0; j < 4; j++) {
                float4 bv = pb[j], lv = pl[j];
                va[4*j]  = fmaxf(va[4*j]   + bv.x + lv.x, 0.f);
                va[4*j+1]= fmaxf(va[4*j+1] + bv.y + lv.y, 0.f);
                va[4*j+2]= fmaxf(va[4*j+2] + bv.z + lv.z, 0.f);
                va[4*j+3]= fmaxf(va[4*j+3] + bv.w + lv.w, 0.f);
            }
        }
    };
    auto fetchB = [&](int t) {
        if (BMODE == 0) {
            // 4 k-rows x 2 n
            #pragma unroll
            for (int kr = 0; kr < 4; kr++) {
                float2 x = *(const float2*)(gB + (size_t)t*32*ldb + (size_t)kr*ldb);
                vb[2*kr] = x.x; vb[2*kr+1] = x.y;
            }
        } else {
            const float4* p = (const float4*)(gB + t*32);
            float4 x0 = p[0], x1 = p[1];
            vb[0]=x0.x; vb[1]=x0.y; vb[2]=x0.z; vb[3]=x0.w;
            vb[4]=x1.x; vb[5]=x1.y; vb[6]=x1.z; vb[7]=x1.w;
        }
    };
    auto stageA = [&](int buf) {
        int base = buf*A_BUF_W + arow*AW2 + ah16*8;
        #pragma unroll
        for (int j = 0; j < 8; j++) {
            uint32_t hi, lo;
            hsplit2(va[2*j], va[2*j+1], hi, lo);
            As[base + j]      = hi;
            As[base + 16 + j] = lo;
        }
    };
    auto stageB = [&](int buf) {
        if (BMODE == 0) {
            // vb = B[4j..4j+3][n0], interleaved with [n0+1]
            // col n0: kpair 2j = (vb0, vb2); kpair 2j+1 = (vb4, vb6)
            int c0 = buf*B_BUF_W + b_n0*AW2;
            int c1 = c0 + AW2;
            uint32_t hi, lo;
            hsplit2(vb[0], vb[2], hi, lo);
            Bs[c0 + 2*b_j] = hi;      Bs[c0 + 16 + 2*b_j] = lo;
            hsplit2(vb[4], vb[6], hi, lo);
            Bs[c0 + 2*b_j+1] = hi;    Bs[c0 + 16 + 2*b_j+1] = lo;
            hsplit2(vb[1], vb[3], hi, lo);
            Bs[c1 + 2*b_j] = hi;      Bs[c1 + 16 + 2*b_j] = lo;
            hsplit2(vb[5], vb[7], hi, lo);
            Bs[c1 + 2*b_j+1] = hi;    Bs[c1 + 16 + 2*b_j+1] = lo;
        } else {
            int base = buf*B_BUF_W + b_nrow*AW2 + b_kq*4;
            #pragma unroll
            for (int j = 0; j < 4; j++) {
                uint32_t hi, lo;
                hsplit2(vb[2*j], vb[2*j+1], hi, lo);
                Bs[base + j]      = hi;
                Bs[base + 16 + j] = lo;
            }
        }
    };

    float acc[2][4][4];
    #pragma unroll
    for (int f = 0; f < 2; f++)
        #pragma unroll
        for (int g = 0; g < 4; g++)
            #pragma unroll
            for (int i = 0; i < 4; i++) acc[f][g][i] = 0.f;

    fetchA(0); fetchB(0);
    stageA(0); stageB(0);
    __syncthreads();

    const int nk = kslice >> 5;
    for (int t = 0; t < nk; t++) {
        int cur = t & 1, nxt = cur ^ 1;
        if (t + 1 < nk) { fetchA(t+1); fetchB(t+1); }

        #pragma unroll
        for (int s = 0; s < 2; s++) {          // two m16n8k16 steps
            uint32_t ah[2][4], al[2][4];
            #pragma unroll
            for (int f = 0; f < 2; f++) {
                int m0 = wm*32 + f*16 + q;
                int w0 = cur*A_BUF_W + m0*AW2 + s*8 + r;
                int w1 = cur*A_BUF_W + (m0+8)*AW2 + s*8 + r;
                ah[f][0] = As[w0];      ah[f][1] = As[w1];
                ah[f][2] = As[w0+4];    ah[f][3] = As[w1+4];
                al[f][0] = As[w0+16];   al[f][1] = As[w1+16];
                al[f][2] = As[w0+20];   al[f][3] = As[w1+20];
            }
            #pragma unroll
            for (int g = 0; g < 4; g++) {
                int nn = wn*32 + g*8 + q;
                int wb = cur*B_BUF_W + nn*AW2 + s*8 + r;
                uint32_t bh[2] = {Bs[wb],    Bs[wb+4]};
                uint32_t bl[2] = {Bs[wb+16], Bs[wb+20]};
                #pragma unroll
                for (int f = 0; f < 2; f++) {
                    mma_f16(acc[f][g], ah[f], bh);
                    mma_f16(acc[f][g], ah[f], bl);
                    mma_f16(acc[f][g], al[f], bh);
                }
            }
        }

        if (t + 1 < nk) { stageA(nxt); stageB(nxt); }
        __syncthreads();
    }

    // epilogue: m16n8 frag: c0 (q,2r), c1 (q,2r+1), c2 (q+8,2r), c3 (q+8,2r+1)
    #pragma unroll
    for (int f = 0; f < 2; f++) {
        int row0 = bm + wm*32 + f*16 + q;
        #pragma unroll
        for (int g = 0; g < 4; g++) {
            int ncol = bn + wn*32 + g*8 + r*2;
            *(float2*)(C + (size_t)row0*N + ncol) =
                make_float2(acc[f][g][0], acc[f][g][1]);
            *(float2*)(C + (size_t)(row0+8)*N + ncol) =
                make_float2(acc[f][g][2], acc[f][g][3]);
        }
    }
}

// ---------------- GEMM wrappers (R8/R11 split config) -----------------------
// L1: Pl1[net*2+kp] = pooled @ W1[net] slice   grid(12,4,4) = 192
__global__ __launch_bounds__(256, 2) void k_l1(
    const float* __restrict__ pooled,
    const float* __restrict__ Wh1, const float* __restrict__ Wt1,
    float* __restrict__ Pl1)
{
    int z = blockIdx.z, net = z >> 1, kp = z & 1;
    gemm_core<0,0>(pooled, nullptr, nullptr, nullptr,
                   nullptr, nullptr, nullptr, D_,
                   net ? Wt1 : Wh1, H1_, H1_, 0,
                   Pl1 + (size_t)z*PL1_SLAB, H1_, kp*384, 384);
}

// L2: Pl2[net*4+kp] = relu(Pl1sum2 + b1 + lb) @ W2[net]   grid(6,4,8) = 192
__global__ __launch_bounds__(256, 2) void k_l2(
    const float* __restrict__ Pl1,
    const float* __restrict__ Wh2, const float* __restrict__ Wt2,
    const float* __restrict__ bh1, const float* __restrict__ bt1,
    const int* __restrict__ labels,
    const float* __restrict__ eph, const float* __restrict__ ept,
    float* __restrict__ Pl2)
{
    int z = blockIdx.z, net = z >> 2, kp = z & 3;
    const float* base = Pl1 + (size_t)(net*2)*PL1_SLAB;
    gemm_core<1,0>(base, base + PL1_SLAB, nullptr, nullptr,
                   net ? bt1 : bh1, labels, net ? ept : eph, H1_,
                   net ? Wt2 : Wh2, H2_, H2_, 0,
                   Pl2 + (size_t)z*PL2_SLAB, H2_, kp*192, 192);
}

// u: Pu[kp] = head @ W_bil (segmented)   grid(12,4,4) = 192
__global__ __launch_bounds__(256, 2) void k_u(
    const float* __restrict__ head, const float* __restrict__ Wbil,
    float* __restrict__ Pu)
{
    int kp = blockIdx.z;
    gemm_core<0,0>(head, nullptr, nullptr, nullptr,
                   nullptr, nullptr, nullptr, H2_,
                   Wbil, H2_, H2_, H2_*H2_,
                   Pu + (size_t)kp*PU_SLAB, 2*H2_, kp*96, 96);
}

// V: Vp[bo*4+kp] = (sum4 Pu)[b,:,o-slice] @ tail_b^T   grid(4,2,16) = 128
__global__ __launch_bounds__(256, 2) void k_V(
    const float* __restrict__ Pu, const float* __restrict__ tail,
    float* __restrict__ Vp)
{
    int z = blockIdx.z, bo = z >> 2, kp = z & 3;
    int b = bo >> 1, o = bo & 1;
    const float* base = Pu + (size_t)(b*E_)*(2*H2_) + o*H2_;
    gemm_core<2,1>(base, base + PU_SLAB, base + 2*PU_SLAB, base + 3*PU_SLAB,
                   nullptr, nullptr, nullptr, 2*H2_,
                   tail + (size_t)b*E_*H2_, H2_, 0, 0,
                   Vp + (size_t)z*E_*E_, E_, kp*96, 96);
}

// ---------------- 1) span mean-pooling --------------------------------------
__global__ void pool_kernel(const float* __restrict__ hs,
                            const int* __restrict__ st,
                            const int* __restrict__ en) {
    int be = blockIdx.x;             // 0..511
    int b  = be >> 8;
    int s  = st[be];
    int len = en[be] - s;
    int cl  = len < 1 ? 1 : len;
    float inv = 1.0f / (float)cl;
    const float* base = hs + ((size_t)(b*T_ + s))*D_;
    for (int d = threadIdx.x; d < D_; d += blockDim.x) {
        float acc = 0.f;
        for (int t = 0; t < len; t++) acc += base[(size_t)t*D_ + d];
        g_pooled[(size_t)be*D_ + d] = acc * inv;
    }
}

// ---------------- 2) per-label projection through W1[768:] for BOTH nets ----
__global__ void labelproj2_kernel(const float* __restrict__ emb,
                                  const float* __restrict__ Wh1,
                                  const float* __restrict__ Wt1) {
    int gid = blockIdx.x*blockDim.x + threadIdx.x;  // 2*5*768 = 7680
    if (gid >= 2*NL_*H1_) return;
    int half = gid / (NL_*H1_);
    int r    = gid - half*(NL_*H1_);
    int l = r / H1_, n = r - l*H1_;
    const float* W1 = half ? Wt1 : Wh1;
    const float* wp = W1 + (size_t)D_*H1_ + n;      // rows 768..1535, col n
    const float* ep = emb + (size_t)l*D_;
    float acc = 0.f;
    #pragma unroll 4
    for (int k = 0; k < D_; k++) acc += ep[k] * wp[(size_t)k*H1_];
    if (half) g_ept[r] = acc; else g_eph[r] = acc;
}

// ---------------- combine L2: head/tail = relu(sum4 Pl2 + bias) -------------
__global__ void combine_l2(const float* __restrict__ Pl2,
                           const float* __restrict__ bh2,
                           const float* __restrict__ bt2,
                           float* __restrict__ head, float* __restrict__ tail)
{
    int idx = blockIdx.x*blockDim.x + threadIdx.x;
    int pq = ROWS_*H2_/4;
    if (idx >= 2*pq) return;
    int net = idx >= pq ? 1 : 0;
    int r = idx - net*pq;
    int col = (r*4) % H2_;
    const float* bs = net ? bt2 : bh2;
    float4 v = make_float4(bs[col], bs[col+1], bs[col+2], bs[col+3]);
    #pragma unroll
    for (int kp = 0; kp < 4; kp++) {
        float4 a = ((const float4*)(Pl2 + (size_t)(net*4+kp)*PL2_SLAB))[r];
        v.x += a.x; v.y += a.y; v.z += a.z; v.w += a.w;
    }
    v.x = fmaxf(v.x, 0.f); v.y = fmaxf(v.y, 0.f);
    v.z = fmaxf(v.z, 0.f); v.w = fmaxf(v.w, 0.f);
    (net ? (float4*)tail : (float4*)head)[r] = v;
}

// ---------------- per-entity linear terms lh/lt -----------------------------
__global__ void lhlt_kernel(const float* __restrict__ Wlin) {
    int gid  = blockIdx.x*blockDim.x + threadIdx.x;
    int w    = gid >> 5;            // entity row 0..511
    int lane = gid & 31;
    if (w >= ROWS_) return;
    float s0=0.f, s1=0.f, s2=0.f, s3=0.f;
    for (int j = lane; j < H2_; j += 32) {
        float hv = g_head[(size_t)w*H2_ + j];
        float tv = g_tail[(size_t)w*H2_ + j];
        s0 += hv * Wlin[j*2+0];
        s1 += hv * Wlin[j*2+1];
        s2 += tv * Wlin[(H2_+j)*2+0];
        s3 += tv * Wlin[(H2_+j)*2+1];
    }
    #pragma unroll
    for (int off = 16; off > 0; off >>= 1) {
        s0 += __shfl_down_sync(0xffffffffu, s0, off);
        s1 += __shfl_down_sync(0xffffffffu, s1, off);
        s2 += __shfl_down_sync(0xffffffffu, s2, off);
        s3 += __shfl_down_sync(0xffffffffu, s3, off);
    }
    if (lane == 0) {
        g_lh[w*2+0] = s0; g_lh[w*2+1] = s1;
        g_lt[w*2+0] = s2; g_lt[w*2+1] = s3;
    }
}

// ---------------- final per-pair lookup (sums 4 V partials per o) -----------
__global__ void gather_kernel(const int* __restrict__ hidx,
                              const int* __restrict__ tidx,
                              const float* __restrict__ blin,
                              float* __restrict__ out) {
    int gid = blockIdx.x*blockDim.x + threadIdx.x;   // B*P = 131072
    if (gid >= B_*P_) return;
    int b = gid >> 16;
    int h = hidx[gid];
    int t = tidx[gid];
    int rh = (b << 8) + h;
    int rt = (b << 8) + t;
    size_t off = (size_t)(h << 8) + t;
    float v0 = 0.f, v1 = 0.f;
    #pragma unroll
    for (int kp = 0; kp < 4; kp++) {
        v0 += g_Vp[(((size_t)(b*2+0)*4 + kp) << 16) + off];
        v1 += g_Vp[(((size_t)(b*2+1)*4 + kp) << 16) + off];
    }
    float2 r;
    r.x = v0 + g_lh[rh*2+0] + g_lt[rt*2+0] + blin[0];
    r.y = v1 + g_lh[rh*2+1] + g_lt[rt*2+1] + blin[1];
    ((float2*)out)[gid] = r;
}

// ---------------- launch ----------------------------------------------------
extern "C" void kernel_launch(void* const* d_in, const int* in_sizes, int n_in,
                              void* d_out, int out_size) {
    const float* hs   = (const float*)d_in[0];
    const float* emb  = (const float*)d_in[1];
    const float* Wh1  = (const float*)d_in[2];
    const float* bh1  = (const float*)d_in[3];
    const float* Wh2  = (const float*)d_in[4];
    const float* bh2  = (const float*)d_in[5];
    const float* Wt1  = (const float*)d_in[6];
    const float* bt1  = (const float*)d_in[7];
    const float* Wt2  = (const float*)d_in[8];
    const float* bt2  = (const float*)d_in[9];
    const float* Wbil = (const float*)d_in[10];
    const float* Wlin = (const float*)d_in[11];
    const float* blin = (const float*)d_in[12];
    const int*   est  = (const int*)d_in[13];
    const int*   een  = (const int*)d_in[14];
    const int*   elab = (const int*)d_in[15];
    const int*   hidx = (const int*)d_in[16];
    const int*   tidx = (const int*)d_in[17];

    float *p_pooled, *p_eph, *p_ept, *p_Pl1, *p_Pl2, *p_head, *p_tail,
          *p_Pu, *p_Vp;
    cudaGetSymbolAddress((void**)&p_pooled, g_pooled);
    cudaGetSymbolAddress((void**)&p_eph,    g_eph);
    cudaGetSymbolAddress((void**)&p_ept,    g_ept);
    cudaGetSymbolAddress((void**)&p_Pl1,    g_Pl1);
    cudaGetSymbolAddress((void**)&p_Pl2,    g_Pl2);
    cudaGetSymbolAddress((void**)&p_head,   g_head);
    cudaGetSymbolAddress((void**)&p_tail,   g_tail);
    cudaGetSymbolAddress((void**)&p_Pu,     g_Pu);
    cudaGetSymbolAddress((void**)&p_Vp,     g_Vp);

    // allow >48KB dynamic smem (non-stream API; capture-safe)
    cudaFuncSetAttribute(k_l1, cudaFuncAttributeMaxDynamicSharedMemorySize, SM_BYTES);
    cudaFuncSetAttribute(k_l2, cudaFuncAttributeMaxDynamicSharedMemorySize, SM_BYTES);
    cudaFuncSetAttribute(k_u,  cudaFuncAttributeMaxDynamicSharedMemorySize, SM_BYTES);
    cudaFuncSetAttribute(k_V,  cudaFuncAttributeMaxDynamicSharedMemorySize, SM_BYTES);

    // 1) span mean pooling -> g_pooled [512,768]
    pool_kernel<<<ROWS_, 256>>>(hs, est, een);

    // 2) label projections for BOTH nets in one launch
    labelproj2_kernel<<<(2*NL_*H1_ + 255)/256, 256>>>(emb, Wh1, Wt1);

    // 3) L1 partials (2 nets x split-K2): 192 blocks
    k_l1<<<dim3(H1_/64, ROWS_/128, 4), 256, SM_BYTES>>>(p_pooled, Wh1, Wt1, p_Pl1);

    // 4) L2 partials with fused L1-combine (2 nets x split-K4): 192 blocks
    k_l2<<<dim3(H2_/64, ROWS_/128, 8), 256, SM_BYTES>>>(
        p_Pl1, Wh2, Wt2, bh1, bt1, elab, p_eph, p_ept, p_Pl2);

    // 5) combine L2 partials -> head/tail
    combine_l2<<<(2*ROWS_*H2_/4 + 255)/256, 256>>>(p_Pl2, bh2, bt2, p_head, p_tail);

    // 6) per-entity linear terms
    lhlt_kernel<<<(ROWS_*32 + 255)/256, 256>>>(Wlin);

    // 7) u partials = head @ W_bil (segmented-B), split-K4: 192 blocks
    k_u<<<dim3((2*H2_)/64, ROWS_/128, 4), 256, SM_BYTES>>>(p_head, Wbil, p_Pu);

    // 8) V partials = (sum4 Pu) @ tail^T, per (b,o) x split-K4: 128 blocks
    k_V<<<dim3(E_/64, E_/128, 16), 256, SM_BYTES>>>(p_Pu, p_tail, p_Vp);

    // 9) per-pair lookup (sums V partials) + linear terms + bias
    gather_kernel<<<(B_*P_ + 255)/256, 256>>>(hidx, tidx, blin, (float*)d_out);
}

// round 13
// speedup vs baseline: 1.5162x; 1.0266x over previous
#include <cuda_runtime.h>
#include <cuda_fp16.h>
#include <cstdint>

// Problem constants (fixed by the reference)
#define B_    2
#define T_    512
#define D_    768
#define E_    256
#define P_    65536
#define H1_   768
#define H2_   384
#define NL_   5
#define ROWS_ (B_*E_)          // 512 fused (b,e) rows

#define PL1_SLAB (ROWS_*H1_)   // 393216
#define PL2_SLAB (ROWS_*H2_)   // 196608
#define PU_SLAB  (ROWS_*2*H2_) // 393216

// ---------------- scratch (static device globals; no allocation) ------------
__device__ float g_eph[NL_*H1_];            // emb @ Wh1[768:]         [5,768]
__device__ float g_ept[NL_*H1_];            // emb @ Wt1[768:]         [5,768]
__device__ float g_Pl1[4*PL1_SLAB];         // L1 partials [net*2+kp]
__device__ float g_Pl2[8*PL2_SLAB];         // L2 partials [net*4+kp]
__device__ float g_head[ROWS_*H2_];         // head_all fp32 (lhlt)
__device__ float g_tail[ROWS_*H2_];         // tail_all fp32 (lhlt)
__device__ float g_Pu[4*PU_SLAB];           // u partials [kp]
__device__ float g_Vp[16*E_*E_];            // V partials [bo*4+kp][256*256]
__device__ float g_lh[ROWS_*2];
__device__ float g_lt[ROWS_*2];

// packed hi/lo half2 planes (u32 = half2 of one k-pair), all 16B aligned
__device__ __align__(16) uint32_t g_pooledP_h[512*384], g_pooledP_l[512*384];
__device__ __align__(16) uint32_t g_W1P_h[2*768*384],  g_W1P_l[2*768*384];
__device__ __align__(16) uint32_t g_W2P_h[2*384*384],  g_W2P_l[2*384*384];
__device__ __align__(16) uint32_t g_WbilP_h[768*192],  g_WbilP_l[768*192];
__device__ __align__(16) uint32_t g_h1P_h[2*512*384],  g_h1P_l[2*512*384];
__device__ __align__(16) uint32_t g_headP_h[512*192],  g_headP_l[512*192];
__device__ __align__(16) uint32_t g_tailP_h[512*192],  g_tailP_l[512*192];
__device__ __align__(16) uint32_t g_UP_h[512*384],     g_UP_l[512*384];

// ---------------- fp16 helpers ----------------------------------------------
__device__ __forceinline__ void mma_f16(float c[4],
                                        const uint32_t a[4],
                                        const uint32_t b[2]) {
    asm volatile(
        "mma.sync.aligned.m16n8k16.row.col.f32.f16.f16.f32 "
        "{%0,%1,%2,%3}, {%4,%5,%6,%7}, {%8,%9}, {%0,%1,%2,%3};"
        : "+f"(c[0]), "+f"(c[1]), "+f"(c[2]), "+f"(c[3])
        : "r"(a[0]), "r"(a[1]), "r"(a[2]), "r"(a[3]), "r"(b[0]), "r"(b[1]));
}
__device__ __forceinline__ uint32_t pk2(__half a, __half b) {
    __half2 t = __halves2half2(a, b);
    return *reinterpret_cast<uint32_t*>(&t);
}
__device__ __forceinline__ void hsplit2(float x0, float x1,
                                        uint32_t& hi, uint32_t& lo) {
    __half h0 = __float2half_rn(x0), h1 = __float2half_rn(x1);
    float l0 = x0 - __half2float(h0);
    float l1 = x1 - __half2float(h1);
    hi = pk2(h0, h1);
    lo = pk2(__float2half_rn(l0), __float2half_rn(l1));
}

// ---------------- cp.async helpers ------------------------------------------
__device__ __forceinline__ uint32_t smem_u32(const void* p) {
    return (uint32_t)__cvta_generic_to_shared(p);
}
__device__ __forceinline__ void cp16(uint32_t dst, const void* src) {
    asm volatile("cp.async.cg.shared.global [%0], [%1], 16;"
                 :: "r"(dst), "l"(src) : "memory");
}
__device__ __forceinline__ void cp_commit() {
    asm volatile("cp.async.commit_group;" ::: "memory");
}
template<int NN> __device__ __forceinline__ void cp_wait() {
    asm volatile("cp.async.wait_group %0;" :: "n"(NN) : "memory");
}

// smem layout identical to R12 (validated): u32 words, stride 36 per row.
// Row: words 0..15 = hi k-pairs 0..15, 16..31 = lo.  A 128 rows, B 64 rows.
#define AW2      36
#define A_BUF_W  (128*AW2)   // 4608
#define B_BUF_W  (64*AW2)    // 2304
#define SM_WORDS (2*A_BUF_W + 2*B_BUF_W)  // 13824 words = 55296 B
#define SM_BYTES (SM_WORDS*4)

// ---------------- packed-operand GEMM core (BK=32, cp.async staging) --------
// C[bm:bm+128, bn:bn+64] = 3-term fp16-split product of packed A,B (NT).
// A planes [M][ldaW] (ldaW = total kpairs), B planes [N][ldbW].
// kpStart in kpairs (multiple of 4), nk = number of 16-kpair tiles.
__device__ __forceinline__ void gemm_core_p(
    const uint32_t* __restrict__ Ahi, const uint32_t* __restrict__ Alo, int ldaW,
    const uint32_t* __restrict__ Bhi, const uint32_t* __restrict__ Blo, int ldbW,
    float* __restrict__ C, int N, int kpStart, int nk)
{
    extern __shared__ uint32_t smw[];
    uint32_t* As = smw;                 // 2 bufs x A_BUF_W
    uint32_t* Bs = smw + 2*A_BUF_W;     // 2 bufs x B_BUF_W

    const int tid = threadIdx.x;
    const int bm = blockIdx.y * 128, bn = blockIdx.x * 64;
    const int lane = tid & 31, wid = tid >> 5;
    const int wm = wid & 3, wn = wid >> 2;     // 4 x 2 warp grid
    const int q = lane >> 2, r = lane & 3;

    // A staging: row = tid>>1, half = tid&1 (8 hi + 8 lo words each)
    const int arow = tid >> 1, ahalf = tid & 1;
    const uint32_t* gAh = Ahi + (size_t)(bm+arow)*ldaW + kpStart + ahalf*8;
    const uint32_t* gAl = Alo + (size_t)(bm+arow)*ldaW + kpStart + ahalf*8;
    const uint32_t sA = smem_u32(As) + (uint32_t)(arow*AW2 + ahalf*8)*4;

    // B staging: row = tid>>2, quarter = tid&3 (4 hi + 4 lo words each)
    const int brow = tid >> 2, bq = tid & 3;
    const uint32_t* gBh = Bhi + (size_t)(bn+brow)*ldbW + kpStart + bq*4;
    const uint32_t* gBl = Blo + (size_t)(bn+brow)*ldbW + kpStart + bq*4;
    const uint32_t sB = smem_u32(Bs) + (uint32_t)(brow*AW2 + bq*4)*4;

    auto issue = [&](int t, int buf) {
        uint32_t a = sA + (uint32_t)buf*(A_BUF_W*4);
        const uint32_t* sh = gAh + t*16;
        const uint32_t* sl = gAl + t*16;
        cp16(a,      sh);     cp16(a + 16, sh + 4);
        cp16(a + 64, sl);     cp16(a + 80, sl + 4);
        uint32_t b = sB + (uint32_t)buf*(B_BUF_W*4);
        cp16(b,      gBh + t*16);
        cp16(b + 64, gBl + t*16);
        cp_commit();
    };

    float acc[2][4][4];
    #pragma unroll
    for (int f = 0; f < 2; f++)
        #pragma unroll
        for (int g = 0; g < 4; g++)
            #pragma unroll
            for (int i = 0; i < 4; i++) acc[f][g][i] = 0.f;

    issue(0, 0);
    if (nk > 1) issue(1, 1);

    for (int t = 0; t < nk; t++) {
        int cur = t & 1;
        if (t + 1 < nk) cp_wait<1>(); else cp_wait<0>();
        __syncthreads();

        // ---- compute tile t from buffer cur (identical to R12 core) ----
        #pragma unroll
        for (int s = 0; s < 2; s++) {
            uint32_t ah[2][4], al[2][4];
            #pragma unroll
            for (int f = 0; f < 2; f++) {
                int m0 = wm*32 + f*16 + q;
                int w0 = cur*A_BUF_W + m0*AW2 + s*8 + r;
                int w1 = cur*A_BUF_W + (m0+8)*AW2 + s*8 + r;
                ah[f][0] = As[w0];      ah[f][1] = As[w1];
                ah[f][2] = As[w0+4];    ah[f][3] = As[w1+4];
                al[f][0] = As[w0+16];   al[f][1] = As[w1+16];
                al[f][2] = As[w0+20];   al[f][3] = As[w1+20];
            }
            #pragma unroll
            for (int g = 0; g < 4; g++) {
                int nn = wn*32 + g*8 + q;
                int wb = cur*B_BUF_W + nn*AW2 + s*8 + r;
                uint32_t bh[2] = {Bs[wb],    Bs[wb+4]};
                uint32_t bl[2] = {Bs[wb+16], Bs[wb+20]};
                #pragma unroll
                for (int f = 0; f < 2; f++) {
                    mma_f16(acc[f][g], ah[f], bh);
                    mma_f16(acc[f][g], ah[f], bl);
                    mma_f16(acc[f][g], al[f], bh);
                }
            }
        }
        __syncthreads();                       // all reads of buf cur done
        if (t + 2 < nk) issue(t + 2, cur);     // refill cur for tile t+2
    }

    // epilogue: m16n8 frag: c0 (q,2r), c1 (q,2r+1), c2 (q+8,2r), c3 (q+8,2r+1)
    #pragma unroll
    for (int f = 0; f < 2; f++) {
        int row0 = bm + wm*32 + f*16 + q;
        #pragma unroll
        for (int g = 0; g < 4; g++) {
            int ncol = bn + wn*32 + g*8 + r*2;
            *(float2*)(C + (size_t)row0*N + ncol) =
                make_float2(acc[f][g][0], acc[f][g][1]);
            *(float2*)(C + (size_t)(row0+8)*N + ncol) =
                make_float2(acc[f][g][2], acc[f][g][3]);
        }
    }
}

// ---------------- GEMM wrappers ---------------------------------------------
// L1: Pl1[net*2+kp] = pooled @ W1[net] slice   grid(12,4,4) = 192
__global__ __launch_bounds__(256, 2) void k_l1(float* __restrict__ Pl1)
{
    int z = blockIdx.z, net = z >> 1, kp = z & 1;
    gemm_core_p(g_pooledP_h, g_pooledP_l, 384,
                g_W1P_h + (size_t)net*768*384, g_W1P_l + (size_t)net*768*384, 384,
                Pl1 + (size_t)z*PL1_SLAB, H1_, kp*192, 12);
}

// L2: Pl2[net*4+kp] = h1[net] @ W2[net]   grid(6,4,8) = 192
__global__ __launch_bounds__(256, 2) void k_l2(float* __restrict__ Pl2)
{
    int z = blockIdx.z, net = z >> 2, kp = z & 3;
    gemm_core_p(g_h1P_h + (size_t)net*512*384, g_h1P_l + (size_t)net*512*384, 384,
                g_W2P_h + (size_t)net*384*384, g_W2P_l + (size_t)net*384*384, 384,
                Pl2 + (size_t)z*PL2_SLAB, H2_, kp*96, 6);
}

// u: Pu[kp] = head @ W_bil   grid(12,4,4) = 192
__global__ __launch_bounds__(256, 2) void k_u(float* __restrict__ Pu)
{
    int kp = blockIdx.z;
    gemm_core_p(g_headP_h, g_headP_l, 192,
                g_WbilP_h, g_WbilP_l, 192,
                Pu + (size_t)kp*PU_SLAB, 2*H2_, kp*48, 3);
}

// V: Vp[bo*4+kp] = U[b,:,o-slice] @ tail_b^T   grid(4,2,16) = 128
__global__ __launch_bounds__(256, 2) void k_V(float* __restrict__ Vp)
{
    int z = blockIdx.z, bo = z >> 2, kp = z & 3;
    int b = bo >> 1, o = bo & 1;
    gemm_core_p(g_UP_h + (size_t)(b*E_)*384 + o*192,
                g_UP_l + (size_t)(b*E_)*384 + o*192, 384,
                g_tailP_h + (size_t)(b*E_)*192,
                g_tailP_l + (size_t)(b*E_)*192, 192,
                Vp + (size_t)z*E_*E_, E_, kp*48, 3);
}

// ---------------- 1) span mean-pooling + pack --------------------------------
__global__ void pool_pack_kernel(const float* __restrict__ hs,
                                 const int* __restrict__ st,
                                 const int* __restrict__ en) {
    int be = blockIdx.x;             // 0..511
    int b  = be >> 8;
    int s  = st[be];
    int len = en[be] - s;
    int cl  = len < 1 ? 1 : len;
    float inv = 1.0f / (float)cl;
    const float* base = hs + ((size_t)(b*T_ + s))*D_;
    for (int dp = threadIdx.x; dp < D_/2; dp += blockDim.x) {
        int d = 2*dp;
        float a0 = 0.f, a1 = 0.f;
        for (int t = 0; t < len; t++) {
            a0 += base[(size_t)t*D_ + d];
            a1 += base[(size_t)t*D_ + d + 1];
        }
        uint32_t hi, lo;
        hsplit2(a0*inv, a1*inv, hi, lo);
        g_pooledP_h[(size_t)be*384 + dp] = hi;
        g_pooledP_l[(size_t)be*384 + dp] = lo;
    }
}

// ---------------- 2) per-label projection (unchanged) ------------------------
__global__ void labelproj2_kernel(const float* __restrict__ emb,
                                  const float* __restrict__ Wh1,
                                  const float* __restrict__ Wt1) {
    int gid = blockIdx.x*blockDim.x + threadIdx.x;  // 2*5*768 = 7680
    if (gid >= 2*NL_*H1_) return;
    int half = gid / (NL_*H1_);
    int r    = gid - half*(NL_*H1_);
    int l = r / H1_, n = r - l*H1_;
    const float* W1 = half ? Wt1 : Wh1;
    const float* wp = W1 + (size_t)D_*H1_ + n;
    const float* ep = emb + (size_t)l*D_;
    float acc = 0.f;
    #pragma unroll 4
    for (int k = 0; k < D_; k++) acc += ep[k] * wp[(size_t)k*H1_];
    if (half) g_ept[r] = acc; else g_eph[r] = acc;
}

// ---------------- 3) weight transpose-pack ----------------------------------
// src fp32 [K][N] (row stride N) -> dstHi/dstLo [N][K/2]. Tile 64k x 32n.
__global__ void pack_w_kernel(const float* __restrict__ Wh1,
                              const float* __restrict__ Wt1,
                              const float* __restrict__ Wh2,
                              const float* __restrict__ Wt2,
                              const float* __restrict__ Wbil) {
    const float* src; int K, N; uint32_t *dh, *dl;
    switch (blockIdx.z) {
        case 0: src = Wh1;            K = 768; N = 768; dh = g_W1P_h;            dl = g_W1P_l;            break;
        case 1: src = Wt1;            K = 768; N = 768; dh = g_W1P_h + 768*384;  dl = g_W1P_l + 768*384;  break;
        case 2: src = Wh2;            K = 768; N = 384; dh = g_W2P_h;            dl = g_W2P_l;            break;
        case 3: src = Wt2;            K = 768; N = 384; dh = g_W2P_h + 384*384;  dl = g_W2P_l + 384*384;  break;
        case 4: src = Wbil;           K = 384; N = 384; dh = g_WbilP_h;          dl = g_WbilP_l;          break;
        default: src = Wbil + 384*384; K = 384; N = 384; dh = g_WbilP_h + 384*192; dl = g_WbilP_l + 384*192; break;
    }
    int kt = blockIdx.y, nt = blockIdx.x;
    if (kt*64 >= K || nt*32 >= N) return;
    __shared__ float sbuf[64][33];
    int tid = threadIdx.x;
    for (int i = tid; i < 64*32; i += 256) {
        int kk = i >> 5, n = i & 31;
        sbuf[kk][n] = src[(size_t)(kt*64 + kk)*N + nt*32 + n];
    }
    __syncthreads();
    int ldW = K >> 1;
    for (int i = tid; i < 32*32; i += 256) {
        int n = i >> 5, p = i & 31;
        uint32_t hi, lo;
        hsplit2(sbuf[2*p][n], sbuf[2*p+1][n], hi, lo);
        size_t off = (size_t)(nt*32 + n)*ldW + kt*32 + p;
        dh[off] = hi;
        dl[off] = lo;
    }
}

// ---------------- combine L1: h1P = pack(relu(sum2 Pl1 + b1 + lbias)) -------
__global__ void combine_l1(const float* __restrict__ bh1,
                           const float* __restrict__ bt1,
                           const int* __restrict__ labels) {
    int gid = blockIdx.x*blockDim.x + threadIdx.x;   // 2*512*384
    if (gid >= 2*512*384) return;
    int net = gid / (512*384);
    int rr  = gid - net*(512*384);
    int row = rr / 384, wp = rr - row*384;
    int col = 2*wp;
    const float* base0 = g_Pl1 + (size_t)(net*2  )*PL1_SLAB + (size_t)row*H1_ + col;
    const float* base1 = g_Pl1 + (size_t)(net*2+1)*PL1_SLAB + (size_t)row*H1_ + col;
    const float* bs = net ? bt1 : bh1;
    const float* lb = (net ? g_ept : g_eph) + (size_t)labels[row]*H1_ + col;
    float v0 = fmaxf(base0[0] + base1[0] + bs[col]   + lb[0], 0.f);
    float v1 = fmaxf(base0[1] + base1[1] + bs[col+1] + lb[1], 0.f);
    uint32_t hi, lo;
    hsplit2(v0, v1, hi, lo);
    g_h1P_h[(size_t)net*512*384 + rr] = hi;
    g_h1P_l[(size_t)net*512*384 + rr] = lo;
}

// ---------------- combine L2: head/tail fp32 + packed ------------------------
__global__ void combine_l2(const float* __restrict__ bh2,
                           const float* __restrict__ bt2) {
    int gid = blockIdx.x*blockDim.x + threadIdx.x;   // 2*512*192
    if (gid >= 2*512*192) return;
    int net = gid / (512*192);
    int rr  = gid - net*(512*192);
    int row = rr / 192, wp = rr - row*192;
    int col = 2*wp;
    const float* bs = net ? bt2 : bh2;
    float v0 = bs[col], v1 = bs[col+1];
    #pragma unroll
    for (int kp = 0; kp < 4; kp++) {
        const float* p = g_Pl2 + (size_t)(net*4+kp)*PL2_SLAB + (size_t)row*H2_ + col;
        v0 += p[0]; v1 += p[1];
    }
    v0 = fmaxf(v0, 0.f); v1 = fmaxf(v1, 0.f);
    uint32_t hi, lo;
    hsplit2(v0, v1, hi, lo);
    if (net) {
        g_tail[(size_t)row*H2_ + col] = v0;
        g_tail[(size_t)row*H2_ + col + 1] = v1;
        g_tailP_h[rr] = hi; g_tailP_l[rr] = lo;
    } else {
        g_head[(size_t)row*H2_ + col] = v0;
        g_head[(size_t)row*H2_ + col + 1] = v1;
        g_headP_h[rr] = hi; g_headP_l[rr] = lo;
    }
}

// ---------------- combine u: UP = pack(sum4 Pu) ------------------------------
__global__ void combine_u() {
    int gid = blockIdx.x*blockDim.x + threadIdx.x;   // 512*384
    if (gid >= 512*384) return;
    int row = gid / 384, wp = gid - row*384;
    int col = 2*wp;
    float v0 = 0.f, v1 = 0.f;
    #pragma unroll
    for (int kp = 0; kp < 4; kp++) {
        const float* p = g_Pu + (size_t)kp*PU_SLAB + (size_t)row*(2*H2_) + col;
        v0 += p[0]; v1 += p[1];
    }
    uint32_t hi, lo;
    hsplit2(v0, v1, hi, lo);
    g_UP_h[gid] = hi;
    g_UP_l[gid] = lo;
}

// ---------------- per-entity linear terms lh/lt -----------------------------
__global__ void lhlt_kernel(const float* __restrict__ Wlin) {
    int gid  = blockIdx.x*blockDim.x + threadIdx.x;
    int w    = gid >> 5;
    int lane = gid & 31;
    if (w >= ROWS_) return;
    float s0=0.f, s1=0.f, s2=0.f, s3=0.f;
    for (int j = lane; j < H2_; j += 32) {
        float hv = g_head[(size_t)w*H2_ + j];
        float tv = g_tail[(size_t)w*H2_ + j];
        s0 += hv * Wlin[j*2+0];
        s1 += hv * Wlin[j*2+1];
        s2 += tv * Wlin[(H2_+j)*2+0];
        s3 += tv * Wlin[(H2_+j)*2+1];
    }
    #pragma unroll
    for (int off = 16; off > 0; off >>= 1) {
        s0 += __shfl_down_sync(0xffffffffu, s0, off);
        s1 += __shfl_down_sync(0xffffffffu, s1, off);
        s2 += __shfl_down_sync(0xffffffffu, s2, off);
        s3 += __shfl_down_sync(0xffffffffu, s3, off);
    }
    if (lane == 0) {
        g_lh[w*2+0] = s0; g_lh[w*2+1] = s1;
        g_lt[w*2+0] = s2; g_lt[w*2+1] = s3;
    }
}

// ---------------- final per-pair lookup (sums 4 V partials per o) -----------
__global__ void gather_kernel(const int* __restrict__ hidx,
                              const int* __restrict__ tidx,
                              const float* __restrict__ blin,
                              float* __restrict__ out) {
    int gid = blockIdx.x*blockDim.x + threadIdx.x;   // B*P = 131072
    if (gid >= B_*P_) return;
    int b = gid >> 16;
    int h = hidx[gid];
    int t = tidx[gid];
    int rh = (b << 8) + h;
    int rt = (b << 8) + t;
    size_t off = (size_t)(h << 8) + t;
    float v0 = 0.f, v1 = 0.f;
    #pragma unroll
    for (int kp = 0; kp < 4; kp++) {
        v0 += g_Vp[(((size_t)(b*2+0)*4 + kp) << 16) + off];
        v1 += g_Vp[(((size_t)(b*2+1)*4 + kp) << 16) + off];
    }
    float2 r;
    r.x = v0 + g_lh[rh*2+0] + g_lt[rt*2+0] + blin[0];
    r.y = v1 + g_lh[rh*2+1] + g_lt[rt*2+1] + blin[1];
    ((float2*)out)[gid] = r;
}

// ---------------- launch ----------------------------------------------------
extern "C" void kernel_launch(void* const* d_in, const int* in_sizes, int n_in,
                              void* d_out, int out_size) {
    const float* hs   = (const float*)d_in[0];
    const float* emb  = (const float*)d_in[1];
    const float* Wh1  = (const float*)d_in[2];
    const float* bh1  = (const float*)d_in[3];
    const float* Wh2  = (const float*)d_in[4];
    const float* bh2  = (const float*)d_in[5];
    const float* Wt1  = (const float*)d_in[6];
    const float* bt1  = (const float*)d_in[7];
    const float* Wt2  = (const float*)d_in[8];
    const float* bt2  = (const float*)d_in[9];
    const float* Wbil = (const float*)d_in[10];
    const float* Wlin = (const float*)d_in[11];
    const float* blin = (const float*)d_in[12];
    const int*   est  = (const int*)d_in[13];
    const int*   een  = (const int*)d_in[14];
    const int*   elab = (const int*)d_in[15];
    const int*   hidx = (const int*)d_in[16];
    const int*   tidx = (const int*)d_in[17];

    float *p_Pl1, *p_Pl2, *p_Pu, *p_Vp;
    cudaGetSymbolAddress((void**)&p_Pl1, g_Pl1);
    cudaGetSymbolAddress((void**)&p_Pl2, g_Pl2);
    cudaGetSymbolAddress((void**)&p_Pu,  g_Pu);
    cudaGetSymbolAddress((void**)&p_Vp,  g_Vp);

    // allow >48KB dynamic smem (non-stream API; capture-safe)
    cudaFuncSetAttribute(k_l1, cudaFuncAttributeMaxDynamicSharedMemorySize, SM_BYTES);
    cudaFuncSetAttribute(k_l2, cudaFuncAttributeMaxDynamicSharedMemorySize, SM_BYTES);
    cudaFuncSetAttribute(k_u,  cudaFuncAttributeMaxDynamicSharedMemorySize, SM_BYTES);
    cudaFuncSetAttribute(k_V,  cudaFuncAttributeMaxDynamicSharedMemorySize, SM_BYTES);

    // 1) span mean pooling -> packed pooledP
    pool_pack_kernel<<<ROWS_, 256>>>(hs, est, een);

    // 2) label projections (fp32)
    labelproj2_kernel<<<(2*NL_*H1_ + 255)/256, 256>>>(emb, Wh1, Wt1);

    // 3) transpose-pack all weights (6 jobs batched on z)
    pack_w_kernel<<<dim3(24, 12, 6), 256>>>(Wh1, Wt1, Wh2, Wt2, Wbil);

    // 4) L1 partials (2 nets x split-K2): 192 blocks
    k_l1<<<dim3(H1_/64, ROWS_/128, 4), 256, SM_BYTES>>>(p_Pl1);

    // 5) combine L1 -> packed h1
    combine_l1<<<(2*512*384 + 255)/256, 256>>>(bh1, bt1, elab);

    // 6) L2 partials (2 nets x split-K4): 192 blocks
    k_l2<<<dim3(H2_/64, ROWS_/128, 8), 256, SM_BYTES>>>(p_Pl2);

    // 7) combine L2 -> head/tail fp32 + packed
    combine_l2<<<(2*512*192 + 255)/256, 256>>>(bh2, bt2);

    // 8) per-entity linear terms
    lhlt_kernel<<<(ROWS_*32 + 255)/256, 256>>>(Wlin);

    // 9) u partials (split-K4): 192 blocks
    k_u<<<dim3((2*H2_)/64, ROWS_/128, 4), 256, SM_BYTES>>>(p_Pu);

    // 10) combine u -> packed U
    combine_u<<<(512*384 + 255)/256, 256>>>();

    // 11) V partials (4 bo x split-K4): 128 blocks
    k_V<<<dim3(E_/64, E_/128, 16), 256, SM_BYTES>>>(p_Vp);

    // 12) per-pair lookup + linear terms + bias
    gather_kernel<<<(B_*P_ + 255)/256, 256>>>(hidx, tidx, blin, (float*)d_out);
}

// round 14
// speedup vs baseline: 1.5469x; 1.0203x over previous
#include <cuda_runtime.h>
#include <cuda_fp16.h>
#include <cstdint>

// Problem constants (fixed by the reference)
#define B_    2
#define T_    512
#define D_    768
#define E_    256
#define P_    65536
#define H1_   768
#define H2_   384
#define NL_   5
#define ROWS_ (B_*E_)          // 512 fused (b,e) rows

#define PL1_SLAB (ROWS_*H1_)   // 393216
#define PL2_SLAB (ROWS_*H2_)   // 196608
#define PU_SLAB  (ROWS_*2*H2_) // 393216

// ---------------- scratch (static device globals; no allocation) ------------
__device__ float g_eph[NL_*H1_];            // emb @ Wh1[768:]         [5,768]
__device__ float g_ept[NL_*H1_];            // emb @ Wt1[768:]         [5,768]
__device__ float g_Pl1[4*PL1_SLAB];         // L1 partials [net*2+kp]
__device__ float g_Pl2[8*PL2_SLAB];         // L2 partials [net*4+kp]
__device__ float g_head[ROWS_*H2_];         // head_all fp32 (lhlt)
__device__ float g_tail[ROWS_*H2_];         // tail_all fp32 (lhlt)
__device__ float g_Pu[4*PU_SLAB];           // u partials [kp]
__device__ float g_Vp[16*E_*E_];            // V partials [bo*4+kp][256*256]
__device__ float g_lh[ROWS_*2];
__device__ float g_lt[ROWS_*2];

// packed hi/lo half2 planes (u32 = half2 of one k-pair), all 16B aligned
__device__ __align__(16) uint32_t g_pooledP_h[512*384], g_pooledP_l[512*384];
__device__ __align__(16) uint32_t g_W1P_h[2*768*384],  g_W1P_l[2*768*384];
__device__ __align__(16) uint32_t g_W2P_h[2*384*384],  g_W2P_l[2*384*384];
__device__ __align__(16) uint32_t g_WbilP_h[768*192],  g_WbilP_l[768*192];
__device__ __align__(16) uint32_t g_h1P_h[2*512*384],  g_h1P_l[2*512*384];
__device__ __align__(16) uint32_t g_headP_h[512*192],  g_headP_l[512*192];
__device__ __align__(16) uint32_t g_tailP_h[512*192],  g_tailP_l[512*192];
__device__ __align__(16) uint32_t g_UP_h[512*384],     g_UP_l[512*384];

// ---------------- fp16 helpers ----------------------------------------------
__device__ __forceinline__ void mma_f16(float c[4],
                                        const uint32_t a[4],
                                        const uint32_t b[2]) {
    asm volatile(
        "mma.sync.aligned.m16n8k16.row.col.f32.f16.f16.f32 "
        "{%0,%1,%2,%3}, {%4,%5,%6,%7}, {%8,%9}, {%0,%1,%2,%3};"
        : "+f"(c[0]), "+f"(c[1]), "+f"(c[2]), "+f"(c[3])
        : "r"(a[0]), "r"(a[1]), "r"(a[2]), "r"(a[3]), "r"(b[0]), "r"(b[1]));
}
__device__ __forceinline__ uint32_t pk2(__half a, __half b) {
    __half2 t = __halves2half2(a, b);
    return *reinterpret_cast<uint32_t*>(&t);
}
__device__ __forceinline__ void hsplit2(float x0, float x1,
                                        uint32_t& hi, uint32_t& lo) {
    __half h0 = __float2half_rn(x0), h1 = __float2half_rn(x1);
    float l0 = x0 - __half2float(h0);
    float l1 = x1 - __half2float(h1);
    hi = pk2(h0, h1);
    lo = pk2(__float2half_rn(l0), __float2half_rn(l1));
}

// ---------------- cp.async helpers ------------------------------------------
__device__ __forceinline__ uint32_t smem_u32(const void* p) {
    return (uint32_t)__cvta_generic_to_shared(p);
}
__device__ __forceinline__ void cp16(uint32_t dst, const void* src) {
    asm volatile("cp.async.cg.shared.global [%0], [%1], 16;"
                 :: "r"(dst), "l"(src) : "memory");
}
__device__ __forceinline__ void cp_commit() {
    asm volatile("cp.async.commit_group;" ::: "memory");
}
template<int NN> __device__ __forceinline__ void cp_wait() {
    asm volatile("cp.async.wait_group %0;" :: "n"(NN) : "memory");
}

// smem layout (validated): u32 words, stride 36 per row.
// Row: words 0..15 = hi k-pairs 0..15, 16..31 = lo.  A 128 rows, B 64 rows.
#define AW2      36
#define A_BUF_W  (128*AW2)   // 4608
#define B_BUF_W  (64*AW2)    // 2304
#define SM_WORDS (2*A_BUF_W + 2*B_BUF_W)  // 13824 words = 55296 B
#define SM_BYTES (SM_WORDS*4)

// ---------------- packed-operand GEMM core (BK=32, cp.async staging) --------
// C[bm:bm+128, bn:bn+64] = 3-term fp16-split product of packed A,B (NT).
// A planes [M][ldaW] (ldaW = total kpairs), B planes [N][ldbW].
// kpStart in kpairs (multiple of 4), nk = number of 16-kpair tiles.
__device__ __forceinline__ void gemm_core_p(
    const uint32_t* __restrict__ Ahi, const uint32_t* __restrict__ Alo, int ldaW,
    const uint32_t* __restrict__ Bhi, const uint32_t* __restrict__ Blo, int ldbW,
    float* __restrict__ C, int N, int kpStart, int nk)
{
    extern __shared__ uint32_t smw[];
    uint32_t* As = smw;                 // 2 bufs x A_BUF_W
    uint32_t* Bs = smw + 2*A_BUF_W;     // 2 bufs x B_BUF_W

    const int tid = threadIdx.x;
    const int bm = blockIdx.y * 128, bn = blockIdx.x * 64;
    const int lane = tid & 31, wid = tid >> 5;
    const int wm = wid & 3, wn = wid >> 2;     // 4 x 2 warp grid
    const int q = lane >> 2, r = lane & 3;

    // A staging: row = tid>>1, half = tid&1 (8 hi + 8 lo words each)
    const int arow = tid >> 1, ahalf = tid & 1;
    const uint32_t* gAh = Ahi + (size_t)(bm+arow)*ldaW + kpStart + ahalf*8;
    const uint32_t* gAl = Alo + (size_t)(bm+arow)*ldaW + kpStart + ahalf*8;
    const uint32_t sA = smem_u32(As) + (uint32_t)(arow*AW2 + ahalf*8)*4;

    // B staging: row = tid>>2, quarter = tid&3 (4 hi + 4 lo words each)
    const int brow = tid >> 2, bq = tid & 3;
    const uint32_t* gBh = Bhi + (size_t)(bn+brow)*ldbW + kpStart + bq*4;
    const uint32_t* gBl = Blo + (size_t)(bn+brow)*ldbW + kpStart + bq*4;
    const uint32_t sB = smem_u32(Bs) + (uint32_t)(brow*AW2 + bq*4)*4;

    auto issue = [&](int t, int buf) {
        uint32_t a = sA + (uint32_t)buf*(A_BUF_W*4);
        const uint32_t* sh = gAh + t*16;
        const uint32_t* sl = gAl + t*16;
        cp16(a,      sh);     cp16(a + 16, sh + 4);
        cp16(a + 64, sl);     cp16(a + 80, sl + 4);
        uint32_t b = sB + (uint32_t)buf*(B_BUF_W*4);
        cp16(b,      gBh + t*16);
        cp16(b + 64, gBl + t*16);
        cp_commit();
    };

    float acc[2][4][4];
    #pragma unroll
    for (int f = 0; f < 2; f++)
        #pragma unroll
        for (int g = 0; g < 4; g++)
            #pragma unroll
            for (int i = 0; i < 4; i++) acc[f][g][i] = 0.f;

    issue(0, 0);
    if (nk > 1) issue(1, 1);

    for (int t = 0; t < nk; t++) {
        int cur = t & 1;
        if (t + 1 < nk) cp_wait<1>(); else cp_wait<0>();
        __syncthreads();

        // ---- compute tile t from buffer cur (validated core) ----
        #pragma unroll
        for (int s = 0; s < 2; s++) {
            uint32_t ah[2][4], al[2][4];
            #pragma unroll
            for (int f = 0; f < 2; f++) {
                int m0 = wm*32 + f*16 + q;
                int w0 = cur*A_BUF_W + m0*AW2 + s*8 + r;
                int w1 = cur*A_BUF_W + (m0+8)*AW2 + s*8 + r;
                ah[f][0] = As[w0];      ah[f][1] = As[w1];
                ah[f][2] = As[w0+4];    ah[f][3] = As[w1+4];
                al[f][0] = As[w0+16];   al[f][1] = As[w1+16];
                al[f][2] = As[w0+20];   al[f][3] = As[w1+20];
            }
            #pragma unroll
            for (int g = 0; g < 4; g++) {
                int nn = wn*32 + g*8 + q;
                int wb = cur*B_BUF_W + nn*AW2 + s*8 + r;
                uint32_t bh[2] = {Bs[wb],    Bs[wb+4]};
                uint32_t bl[2] = {Bs[wb+16], Bs[wb+20]};
                #pragma unroll
                for (int f = 0; f < 2; f++) {
                    mma_f16(acc[f][g], ah[f], bh);
                    mma_f16(acc[f][g], ah[f], bl);
                    mma_f16(acc[f][g], al[f], bh);
                }
            }
        }
        __syncthreads();                       // all reads of buf cur done
        if (t + 2 < nk) issue(t + 2, cur);     // refill cur for tile t+2
    }

    // epilogue: m16n8 frag: c0 (q,2r), c1 (q,2r+1), c2 (q+8,2r), c3 (q+8,2r+1)
    #pragma unroll
    for (int f = 0; f < 2; f++) {
        int row0 = bm + wm*32 + f*16 + q;
        #pragma unroll
        for (int g = 0; g < 4; g++) {
            int ncol = bn + wn*32 + g*8 + r*2;
            *(float2*)(C + (size_t)row0*N + ncol) =
                make_float2(acc[f][g][0], acc[f][g][1]);
            *(float2*)(C + (size_t)(row0+8)*N + ncol) =
                make_float2(acc[f][g][2], acc[f][g][3]);
        }
    }
}

// ---------------- GEMM wrappers (3 blocks/SM target) -------------------------
// L1: Pl1[net*2+kp] = pooled @ W1[net] slice   grid(12,4,4) = 192
__global__ __launch_bounds__(256, 3) void k_l1(float* __restrict__ Pl1)
{
    int z = blockIdx.z, net = z >> 1, kp = z & 1;
    gemm_core_p(g_pooledP_h, g_pooledP_l, 384,
                g_W1P_h + (size_t)net*768*384, g_W1P_l + (size_t)net*768*384, 384,
                Pl1 + (size_t)z*PL1_SLAB, H1_, kp*192, 12);
}

// L2: Pl2[net*4+kp] = h1[net] @ W2[net]   grid(6,4,8) = 192
__global__ __launch_bounds__(256, 3) void k_l2(float* __restrict__ Pl2)
{
    int z = blockIdx.z, net = z >> 2, kp = z & 3;
    gemm_core_p(g_h1P_h + (size_t)net*512*384, g_h1P_l + (size_t)net*512*384, 384,
                g_W2P_h + (size_t)net*384*384, g_W2P_l + (size_t)net*384*384, 384,
                Pl2 + (size_t)z*PL2_SLAB, H2_, kp*96, 6);
}

// u: Pu[kp] = head @ W_bil   grid(12,4,4) = 192
__global__ __launch_bounds__(256, 3) void k_u(float* __restrict__ Pu)
{
    int kp = blockIdx.z;
    gemm_core_p(g_headP_h, g_headP_l, 192,
                g_WbilP_h, g_WbilP_l, 192,
                Pu + (size_t)kp*PU_SLAB, 2*H2_, kp*48, 3);
}

// V: Vp[bo*4+kp] = U[b,:,o-slice] @ tail_b^T   grid(4,2,16) = 128
__global__ __launch_bounds__(256, 3) void k_V(float* __restrict__ Vp)
{
    int z = blockIdx.z, bo = z >> 2, kp = z & 3;
    int b = bo >> 1, o = bo & 1;
    gemm_core_p(g_UP_h + (size_t)(b*E_)*384 + o*192,
                g_UP_l + (size_t)(b*E_)*384 + o*192, 384,
                g_tailP_h + (size_t)(b*E_)*192,
                g_tailP_l + (size_t)(b*E_)*192, 192,
                Vp + (size_t)z*E_*E_, E_, kp*48, 3);
}

// ---------------- merged prep: pool-pack + labelproj + weight-pack -----------
// Blocks 0..511:       span mean-pool + pack -> pooledP
// Blocks 512..541:     label projection (fp32), 7680 threads
// Blocks 542..1549:    weight transpose-pack jobs (1008 tiles)
#define PREP_POOL   512
#define PREP_LPROJ  (PREP_POOL + 30)
#define PREP_TOTAL  (PREP_LPROJ + 1008)

__global__ void prep_kernel(const float* __restrict__ hs,
                            const int* __restrict__ st,
                            const int* __restrict__ en,
                            const float* __restrict__ emb,
                            const float* __restrict__ Wh1,
                            const float* __restrict__ Wt1,
                            const float* __restrict__ Wh2,
                            const float* __restrict__ Wt2,
                            const float* __restrict__ Wbil) {
    __shared__ float sbuf[64][33];
    int bz = blockIdx.x;
    int tid = threadIdx.x;

    if (bz < PREP_POOL) {
        // ---- pool + pack ----
        int be = bz;
        int b  = be >> 8;
        int s  = st[be];
        int len = en[be] - s;
        int cl  = len < 1 ? 1 : len;
        float inv = 1.0f / (float)cl;
        const float* base = hs + ((size_t)(b*T_ + s))*D_;
        for (int dp = tid; dp < D_/2; dp += blockDim.x) {
            int d = 2*dp;
            float a0 = 0.f, a1 = 0.f;
            for (int t = 0; t < len; t++) {
                a0 += base[(size_t)t*D_ + d];
                a1 += base[(size_t)t*D_ + d + 1];
            }
            uint32_t hi, lo;
            hsplit2(a0*inv, a1*inv, hi, lo);
            g_pooledP_h[(size_t)be*384 + dp] = hi;
            g_pooledP_l[(size_t)be*384 + dp] = lo;
        }
        return;
    }
    if (bz < PREP_LPROJ) {
        // ---- label projection ----
        int gid = (bz - PREP_POOL)*256 + tid;      // < 7680 = 2*NL*H1
        int half = gid / (NL_*H1_);
        int rr   = gid - half*(NL_*H1_);
        int l = rr / H1_, n = rr - l*H1_;
        const float* W1 = half ? Wt1 : Wh1;
        const float* wp = W1 + (size_t)D_*H1_ + n;
        const float* ep = emb + (size_t)l*D_;
        float acc = 0.f;
        #pragma unroll 4
        for (int k = 0; k < D_; k++) acc += ep[k] * wp[(size_t)k*H1_];
        if (half) g_ept[rr] = acc; else g_eph[rr] = acc;
        return;
    }

    // ---- weight transpose-pack: job id -> (matrix, kt, nt) ----
    int job = bz - PREP_LPROJ;
    const float* src; int K, N; uint32_t *dh, *dl; int local;
    if (job < 288)      { src = Wh1;            K=768; N=768; dh=g_W1P_h;             dl=g_W1P_l;             local=job; }
    else if (job < 576) { src = Wt1;            K=768; N=768; dh=g_W1P_h+768*384;     dl=g_W1P_l+768*384;     local=job-288; }
    else if (job < 720) { src = Wh2;            K=768; N=384; dh=g_W2P_h;             dl=g_W2P_l;             local=job-576; }
    else if (job < 864) { src = Wt2;            K=768; N=384; dh=g_W2P_h+384*384;     dl=g_W2P_l+384*384;     local=job-720; }
    else if (job < 936) { src = Wbil;           K=384; N=384; dh=g_WbilP_h;           dl=g_WbilP_l;           local=job-864; }
    else                { src = Wbil+384*384;   K=384; N=384; dh=g_WbilP_h+384*192;   dl=g_WbilP_l+384*192;   local=job-936; }
    int ntiles = N >> 5;
    int kt = local / ntiles, nt = local - kt*ntiles;

    for (int i = tid; i < 64*32; i += 256) {
        int kk = i >> 5, n = i & 31;
        sbuf[kk][n] = src[(size_t)(kt*64 + kk)*N + nt*32 + n];
    }
    __syncthreads();
    int ldW = K >> 1;
    for (int i = tid; i < 32*32; i += 256) {
        int n = i >> 5, p = i & 31;
        uint32_t hi, lo;
        hsplit2(sbuf[2*p][n], sbuf[2*p+1][n], hi, lo);
        size_t off = (size_t)(nt*32 + n)*ldW + kt*32 + p;
        dh[off] = hi;
        dl[off] = lo;
    }
}

// ---------------- combine L1: h1P = pack(relu(sum2 Pl1 + b1 + lbias)) -------
__global__ void combine_l1(const float* __restrict__ bh1,
                           const float* __restrict__ bt1,
                           const int* __restrict__ labels) {
    int gid = blockIdx.x*blockDim.x + threadIdx.x;   // 2*512*384
    if (gid >= 2*512*384) return;
    int net = gid / (512*384);
    int rr  = gid - net*(512*384);
    int row = rr / 384, wp = rr - row*384;
    int col = 2*wp;
    const float* base0 = g_Pl1 + (size_t)(net*2  )*PL1_SLAB + (size_t)row*H1_ + col;
    const float* base1 = g_Pl1 + (size_t)(net*2+1)*PL1_SLAB + (size_t)row*H1_ + col;
    const float* bs = net ? bt1 : bh1;
    const float* lb = (net ? g_ept : g_eph) + (size_t)labels[row]*H1_ + col;
    float v0 = fmaxf(base0[0] + base1[0] + bs[col]   + lb[0], 0.f);
    float v1 = fmaxf(base0[1] + base1[1] + bs[col+1] + lb[1], 0.f);
    uint32_t hi, lo;
    hsplit2(v0, v1, hi, lo);
    g_h1P_h[(size_t)net*512*384 + rr] = hi;
    g_h1P_l[(size_t)net*512*384 + rr] = lo;
}

// ---------------- combine L2: head/tail fp32 + packed ------------------------
__global__ void combine_l2(const float* __restrict__ bh2,
                           const float* __restrict__ bt2) {
    int gid = blockIdx.x*blockDim.x + threadIdx.x;   // 2*512*192
    if (gid >= 2*512*192) return;
    int net = gid / (512*192);
    int rr  = gid - net*(512*192);
    int row = rr / 192, wp = rr - row*192;
    int col = 2*wp;
    const float* bs = net ? bt2 : bh2;
    float v0 = bs[col], v1 = bs[col+1];
    #pragma unroll
    for (int kp = 0; kp < 4; kp++) {
        const float* p = g_Pl2 + (size_t)(net*4+kp)*PL2_SLAB + (size_t)row*H2_ + col;
        v0 += p[0]; v1 += p[1];
    }
    v0 = fmaxf(v0, 0.f); v1 = fmaxf(v1, 0.f);
    uint32_t hi, lo;
    hsplit2(v0, v1, hi, lo);
    if (net) {
        g_tail[(size_t)row*H2_ + col] = v0;
        g_tail[(size_t)row*H2_ + col + 1] = v1;
        g_tailP_h[rr] = hi; g_tailP_l[rr] = lo;
    } else {
        g_head[(size_t)row*H2_ + col] = v0;
        g_head[(size_t)row*H2_ + col + 1] = v1;
        g_headP_h[rr] = hi; g_headP_l[rr] = lo;
    }
}

// ---------------- combine u: UP = pack(sum4 Pu) ------------------------------
__global__ void combine_u() {
    int gid = blockIdx.x*blockDim.x + threadIdx.x;   // 512*384
    if (gid >= 512*384) return;
    int row = gid / 384, wp = gid - row*384;
    int col = 2*wp;
    float v0 = 0.f, v1 = 0.f;
    #pragma unroll
    for (int kp = 0; kp < 4; kp++) {
        const float* p = g_Pu + (size_t)kp*PU_SLAB + (size_t)row*(2*H2_) + col;
        v0 += p[0]; v1 += p[1];
    }
    uint32_t hi, lo;
    hsplit2(v0, v1, hi, lo);
    g_UP_h[gid] = hi;
    g_UP_l[gid] = lo;
}

// ---------------- per-entity linear terms lh/lt -----------------------------
__global__ void lhlt_kernel(const float* __restrict__ Wlin) {
    int gid  = blockIdx.x*blockDim.x + threadIdx.x;
    int w    = gid >> 5;
    int lane = gid & 31;
    if (w >= ROWS_) return;
    float s0=0.f, s1=0.f, s2=0.f, s3=0.f;
    for (int j = lane; j < H2_; j += 32) {
        float hv = g_head[(size_t)w*H2_ + j];
        float tv = g_tail[(size_t)w*H2_ + j];
        s0 += hv * Wlin[j*2+0];
        s1 += hv * Wlin[j*2+1];
        s2 += tv * Wlin[(H2_+j)*2+0];
        s3 += tv * Wlin[(H2_+j)*2+1];
    }
    #pragma unroll
    for (int off = 16; off > 0; off >>= 1) {
        s0 += __shfl_down_sync(0xffffffffu, s0, off);
        s1 += __shfl_down_sync(0xffffffffu, s1, off);
        s2 += __shfl_down_sync(0xffffffffu, s2, off);
        s3 += __shfl_down_sync(0xffffffffu, s3, off);
    }
    if (lane == 0) {
        g_lh[w*2+0] = s0; g_lh[w*2+1] = s1;
        g_lt[w*2+0] = s2; g_lt[w*2+1] = s3;
    }
}

// ---------------- final per-pair lookup (sums 4 V partials per o) -----------
__global__ void gather_kernel(const int* __restrict__ hidx,
                              const int* __restrict__ tidx,
                              const float* __restrict__ blin,
                              float* __restrict__ out) {
    int gid = blockIdx.x*blockDim.x + threadIdx.x;   // B*P = 131072
    if (gid >= B_*P_) return;
    int b = gid >> 16;
    int h = hidx[gid];
    int t = tidx[gid];
    int rh = (b << 8) + h;
    int rt = (b << 8) + t;
    size_t off = (size_t)(h << 8) + t;
    float v0 = 0.f, v1 = 0.f;
    #pragma unroll
    for (int kp = 0; kp < 4; kp++) {
        v0 += g_Vp[(((size_t)(b*2+0)*4 + kp) << 16) + off];
        v1 += g_Vp[(((size_t)(b*2+1)*4 + kp) << 16) + off];
    }
    float2 r;
    r.x = v0 + g_lh[rh*2+0] + g_lt[rt*2+0] + blin[0];
    r.y = v1 + g_lh[rh*2+1] + g_lt[rt*2+1] + blin[1];
    ((float2*)out)[gid] = r;
}

// ---------------- launch ----------------------------------------------------
extern "C" void kernel_launch(void* const* d_in, const int* in_sizes, int n_in,
                              void* d_out, int out_size) {
    const float* hs   = (const float*)d_in[0];
    const float* emb  = (const float*)d_in[1];
    const float* Wh1  = (const float*)d_in[2];
    const float* bh1  = (const float*)d_in[3];
    const float* Wh2  = (const float*)d_in[4];
    const float* bh2  = (const float*)d_in[5];
    const float* Wt1  = (const float*)d_in[6];
    const float* bt1  = (const float*)d_in[7];
    const float* Wt2  = (const float*)d_in[8];
    const float* bt2  = (const float*)d_in[9];
    const float* Wbil = (const float*)d_in[10];
    const float* Wlin = (const float*)d_in[11];
    const float* blin = (const float*)d_in[12];
    const int*   est  = (const int*)d_in[13];
    const int*   een  = (const int*)d_in[14];
    const int*   elab = (const int*)d_in[15];
    const int*   hidx = (const int*)d_in[16];
    const int*   tidx = (const int*)d_in[17];

    float *p_Pl1, *p_Pl2, *p_Pu, *p_Vp;
    cudaGetSymbolAddress((void**)&p_Pl1, g_Pl1);
    cudaGetSymbolAddress((void**)&p_Pl2, g_Pl2);
    cudaGetSymbolAddress((void**)&p_Pu,  g_Pu);
    cudaGetSymbolAddress((void**)&p_Vp,  g_Vp);

    // allow >48KB dynamic smem (non-stream API; capture-safe)
    cudaFuncSetAttribute(k_l1, cudaFuncAttributeMaxDynamicSharedMemorySize, SM_BYTES);
    cudaFuncSetAttribute(k_l2, cudaFuncAttributeMaxDynamicSharedMemorySize, SM_BYTES);
    cudaFuncSetAttribute(k_u,  cudaFuncAttributeMaxDynamicSharedMemorySize, SM_BYTES);
    cudaFuncSetAttribute(k_V,  cudaFuncAttributeMaxDynamicSharedMemorySize, SM_BYTES);

    // 1) merged prep: pool-pack + label projections + weight transpose-pack
    prep_kernel<<<PREP_TOTAL, 256>>>(hs, est, een, emb, Wh1, Wt1, Wh2, Wt2, Wbil);

    // 2) L1 partials (2 nets x split-K2): 192 blocks
    k_l1<<<dim3(H1_/64, ROWS_/128, 4), 256, SM_BYTES>>>(p_Pl1);

    // 3) combine L1 -> packed h1
    combine_l1<<<(2*512*384 + 255)/256, 256>>>(bh1, bt1, elab);

    // 4) L2 partials (2 nets x split-K4): 192 blocks
    k_l2<<<dim3(H2_/64, ROWS_/128, 8), 256, SM_BYTES>>>(p_Pl2);

    // 5) combine L2 -> head/tail fp32 + packed
    combine_l2<<<(2*512*192 + 255)/256, 256>>>(bh2, bt2);

    // 6) per-entity linear terms
    lhlt_kernel<<<(ROWS_*32 + 255)/256, 256>>>(Wlin);

    // 7) u partials (split-K4): 192 blocks
    k_u<<<dim3((2*H2_)/64, ROWS_/128, 4), 256, SM_BYTES>>>(p_Pu);

    // 8) combine u -> packed U
    combine_u<<<(512*384 + 255)/256, 256>>>();

    // 9) V partials (4 bo x split-K4): 128 blocks
    k_V<<<dim3(E_/64, E_/128, 16), 256, SM_BYTES>>>(p_Vp);

    // 10) per-pair lookup + linear terms + bias
    gather_kernel<<<(B_*P_ + 255)/256, 256>>>(hidx, tidx, blin, (float*)d_out);
}